// round 7
// baseline (speedup 1.0000x reference)
#include <cuda_runtime.h>
#include <cstdint>

#define NN 50000
#define NE 500000
#define HH 128

// ---------------- scratch (device globals; no cudaMalloc allowed) ----------------
__device__ float g_U[NN * HH];
__device__ float g_V[NN * HH];
__device__ float g_WE[(long)NE * HH];   // holds ea@W1c+b1, then overwritten with relu(h)
__device__ float g_S[NN * HH];          // segment sum of relu(h)
__device__ float g_INTRA[NN * HH];
__device__ float g_HID[NN * 2 * HH];
__device__ float g_XA[NN * HH];
__device__ float g_XB[NN * HH];
__device__ float g_POS[NN * 3];
__device__ float g_POSACC[NN * 3];
__device__ float g_W[NE];               // per-edge scalar w
__device__ float g_DEG[NN];
__device__ float g_DINV[NN];
__device__ float g_BMASK[NN];
__device__ float g_C[HH * 256];         // W2 @ aW1
__device__ float g_D[256];              // b2 @ aW1 + ab1
__device__ int   g_SRC[NE];
__device__ int   g_DST[NE];

// ---------------- tf32 helpers ----------------------------------------------------
__device__ __forceinline__ unsigned f2tf(float f) {
    unsigned r;
    asm("cvt.rna.tf32.f32 %0, %1;" : "=r"(r) : "f"(f));
    return r;
}

__device__ __forceinline__ void mma8(float c[4],
                                     unsigned a0, unsigned a1, unsigned a2, unsigned a3,
                                     unsigned b0, unsigned b1) {
    asm("mma.sync.aligned.m16n8k8.row.col.f32.tf32.tf32.f32 "
        "{%0,%1,%2,%3},{%4,%5,%6,%7},{%8,%9},{%0,%1,%2,%3};"
        : "+f"(c[0]), "+f"(c[1]), "+f"(c[2]), "+f"(c[3])
        : "r"(a0), "r"(a1), "r"(a2), "r"(a3), "r"(b0), "r"(b1));
}

// -------- index normalization: handles harness storing edge_index as int32 OR int64
__global__ void convert_idx(const int* __restrict__ ei32, int* __restrict__ SRC,
                            int* __restrict__ DST)
{
    bool is64 = (ei32[1] == 0 && ei32[3] == 0 && ei32[5] == 0 && ei32[7] == 0);
    int e = blockIdx.x * blockDim.x + threadIdx.x;
    if (e >= NE) return;
    if (is64) {
        const long long* e64 = (const long long*)ei32;
        SRC[e] = (int)e64[e];
        DST[e] = (int)e64[NE + e];
    } else {
        SRC[e] = ei32[e];
        DST[e] = ei32[NE + e];
    }
}

// ---------------- tf32 tensor-core GEMM: 64(M) x 128(N) block, 256 threads --------
// 8 warps in 2(M) x 4(N); warp tile 32x32; mma m16n8k8.
// C[m,j] = (A_logical[m,:] @ B)[j] * rowscale[m] + bias[j]*rowmask[m]; optional relu.
// If A2 != null: logical A row = concat(A[m,0:128], A2[m,0:128]) (K must be 256,
// both row stride 128). Otherwise A row stride = K.
// sA layout: [ksub(2)][mtile(4)][lane(32)][slot(4)]  (slot = a0..a3 of the fragment)
// sB layout: [ksub(2)][ntile(16)][lane(32)][slot(2)] (slot = b0,b1)
__global__ void __launch_bounds__(256) gemm_tf32(
    const float* __restrict__ A, const float* __restrict__ A2,
    const float* __restrict__ B, const float* __restrict__ bias,
    float* __restrict__ Cout, int M, int K, int Ncols,
    int reluFlag, const float* __restrict__ rowscale, const float* __restrict__ rowmask)
{
    __shared__ unsigned sA[2 * 4 * 32 * 4];
    __shared__ unsigned sB[2 * 16 * 32 * 2];
    const int bm = blockIdx.y * 64;
    const int bn = blockIdx.x * 128;
    const int tid = threadIdx.x;
    const int lane = tid & 31;
    const int warp = tid >> 5;
    const int wm = warp >> 2;     // 0..1
    const int wn = warp & 3;      // 0..3

    float acc[2][4][4];
#pragma unroll
    for (int i = 0; i < 2; i++)
#pragma unroll
        for (int j = 0; j < 4; j++)
#pragma unroll
            for (int q = 0; q < 4; q++) acc[i][j][q] = 0.f;

    const int arow = tid >> 2;          // 0..63
    const int ak4 = (tid & 3) << 2;     // 0,4,8,12

    for (int k0 = 0; k0 < K; k0 += 16) {
        // ---- stage A (64x16) ----
        {
            float4 av = make_float4(0.f, 0.f, 0.f, 0.f);
            int grow = bm + arow;
            if (grow < M) {
                int gk = k0 + ak4;
                const float* src;
                if (A2) src = (gk < HH) ? (A + (long)grow * HH + gk)
                                        : (A2 + (long)grow * HH + (gk - HH));
                else    src = A + (long)grow * K + gk;
                av = *(const float4*)src;
            }
            int ksub  = ak4 >> 3;
            int chalf = (ak4 >> 2) & 1;
            int mtile = arow >> 4, rr = arow & 15;
            int slot  = (rr >> 3) + (chalf << 1);
            int lbase = (rr & 7) << 2;
            unsigned* dst = &sA[(((ksub << 2) + mtile) << 7) + slot];
            dst[(lbase + 0) << 2] = f2tf(av.x);
            dst[(lbase + 1) << 2] = f2tf(av.y);
            dst[(lbase + 2) << 2] = f2tf(av.z);
            dst[(lbase + 3) << 2] = f2tf(av.w);
        }
        // ---- stage B (16x128) ----
#pragma unroll
        for (int p = 0; p < 2; p++) {
            int idx = (p * 256 + tid) << 2;   // 0..2044
            int bk = idx >> 7;                // 0..15
            int n4 = idx & 127;
            float4 bv = *(const float4*)(B + (long)(k0 + bk) * Ncols + bn + n4);
            int ksub = bk >> 3, c = bk & 7;
            int slot = c >> 2;
            int ntile = n4 >> 3;
            int lbase = ((n4 & 7) << 2) + (c & 3);
            unsigned* dst = &sB[(((ksub << 4) + ntile) << 6) + slot];
            dst[(lbase + 0) << 1] = f2tf(bv.x);
            dst[(lbase + 4) << 1] = f2tf(bv.y);
            dst[(lbase + 8) << 1] = f2tf(bv.z);
            dst[(lbase + 12) << 1] = f2tf(bv.w);
        }
        __syncthreads();
        // ---- compute ----
#pragma unroll
        for (int ks = 0; ks < 2; ks++) {
            unsigned a[2][4];
#pragma unroll
            for (int it = 0; it < 2; it++) {
                uint4 v = *(const uint4*)&sA[(((ks << 2) + (wm * 2 + it)) << 7) + (lane << 2)];
                a[it][0] = v.x; a[it][1] = v.y; a[it][2] = v.z; a[it][3] = v.w;
            }
#pragma unroll
            for (int jt = 0; jt < 4; jt++) {
                uint2 b = *(const uint2*)&sB[(((ks << 4) + (wn * 4 + jt)) << 6) + (lane << 1)];
#pragma unroll
                for (int it = 0; it < 2; it++)
                    mma8(acc[it][jt], a[it][0], a[it][1], a[it][2], a[it][3], b.x, b.y);
            }
        }
        __syncthreads();
    }

    // ---- epilogue ----
#pragma unroll
    for (int it = 0; it < 2; it++) {
        int row0 = bm + wm * 32 + it * 16 + (lane >> 2);
#pragma unroll
        for (int h = 0; h < 2; h++) {
            int row = row0 + h * 8;
            if (row >= M) continue;
            float rs = rowscale ? rowscale[row] : 1.f;
            float rm = rowmask ? rowmask[row] : 1.f;
#pragma unroll
            for (int jt = 0; jt < 4; jt++) {
                int col = bn + wn * 32 + jt * 8 + ((lane & 3) << 1);
                float v0 = acc[it][jt][h * 2 + 0] * rs;
                float v1 = acc[it][jt][h * 2 + 1] * rs;
                if (bias) { v0 += bias[col] * rm; v1 += bias[col + 1] * rm; }
                if (reluFlag) { v0 = fmaxf(v0, 0.f); v1 = fmaxf(v1, 0.f); }
                *(float2*)(Cout + (long)row * Ncols + col) = make_float2(v0, v1);
            }
        }
    }
}

// -------- fused edge-acc GEMM (tf32): w[e] = sum_j relu(R[e]@C + D)[j]*aW2[j] -----
// Block: 64 edges x 256 cols, K=128. 8 warps 2x4, warp tile 32x64 (8 ntiles/warp).
__global__ void __launch_bounds__(256) edge_acc_tf32(
    const float* __restrict__ R, const float* __restrict__ Cm,
    const float* __restrict__ D, const float* __restrict__ aW2,
    float* __restrict__ Wout)
{
    __shared__ unsigned sA[2 * 4 * 32 * 4];
    __shared__ unsigned sB[2 * 32 * 32 * 2];
    __shared__ float red[64][4];
    const int bm = blockIdx.x * 64;
    const int tid = threadIdx.x;
    const int lane = tid & 31;
    const int warp = tid >> 5;
    const int wm = warp >> 2;
    const int wn = warp & 3;

    float acc[2][8][4];
#pragma unroll
    for (int i = 0; i < 2; i++)
#pragma unroll
        for (int j = 0; j < 8; j++)
#pragma unroll
            for (int q = 0; q < 4; q++) acc[i][j][q] = 0.f;

    const int arow = tid >> 2;
    const int ak4 = (tid & 3) << 2;

    for (int k0 = 0; k0 < 128; k0 += 16) {
        // stage A from R
        {
            float4 av = make_float4(0.f, 0.f, 0.f, 0.f);
            int grow = bm + arow;
            if (grow < NE) av = *(const float4*)(R + (long)grow * HH + k0 + ak4);
            int ksub  = ak4 >> 3;
            int chalf = (ak4 >> 2) & 1;
            int mtile = arow >> 4, rr = arow & 15;
            int slot  = (rr >> 3) + (chalf << 1);
            int lbase = (rr & 7) << 2;
            unsigned* dst = &sA[(((ksub << 2) + mtile) << 7) + slot];
            dst[(lbase + 0) << 2] = f2tf(av.x);
            dst[(lbase + 1) << 2] = f2tf(av.y);
            dst[(lbase + 2) << 2] = f2tf(av.z);
            dst[(lbase + 3) << 2] = f2tf(av.w);
        }
        // stage B (16x256)
#pragma unroll
        for (int p = 0; p < 4; p++) {
            int idx = (p * 256 + tid) << 2;   // 0..4092
            int bk = idx >> 8;                // 0..15
            int n4 = idx & 255;
            float4 bv = *(const float4*)(Cm + (long)(k0 + bk) * 256 + n4);
            int ksub = bk >> 3, c = bk & 7;
            int slot = c >> 2;
            int ntile = n4 >> 3;
            int lbase = ((n4 & 7) << 2) + (c & 3);
            unsigned* dst = &sB[(((ksub << 5) + ntile) << 6) + slot];
            dst[(lbase + 0) << 1] = f2tf(bv.x);
            dst[(lbase + 4) << 1] = f2tf(bv.y);
            dst[(lbase + 8) << 1] = f2tf(bv.z);
            dst[(lbase + 12) << 1] = f2tf(bv.w);
        }
        __syncthreads();
#pragma unroll
        for (int ks = 0; ks < 2; ks++) {
            unsigned a[2][4];
#pragma unroll
            for (int it = 0; it < 2; it++) {
                uint4 v = *(const uint4*)&sA[(((ks << 2) + (wm * 2 + it)) << 7) + (lane << 2)];
                a[it][0] = v.x; a[it][1] = v.y; a[it][2] = v.z; a[it][3] = v.w;
            }
#pragma unroll
            for (int jt = 0; jt < 8; jt++) {
                uint2 b = *(const uint2*)&sB[(((ks << 5) + (wn * 8 + jt)) << 6) + (lane << 1)];
#pragma unroll
                for (int it = 0; it < 2; it++)
                    mma8(acc[it][jt], a[it][0], a[it][1], a[it][2], a[it][3], b.x, b.y);
            }
        }
        __syncthreads();
    }

    // epilogue: relu(acc + D)*aW2, reduce across cols
#pragma unroll
    for (int it = 0; it < 2; it++) {
        float s0 = 0.f, s1 = 0.f;
#pragma unroll
        for (int jt = 0; jt < 8; jt++) {
            int col = wn * 64 + jt * 8 + ((lane & 3) << 1);
            float d0 = D[col], d1 = D[col + 1];
            float w0 = aW2[col], w1 = aW2[col + 1];
            s0 += fmaxf(acc[it][jt][0] + d0, 0.f) * w0 + fmaxf(acc[it][jt][1] + d1, 0.f) * w1;
            s1 += fmaxf(acc[it][jt][2] + d0, 0.f) * w0 + fmaxf(acc[it][jt][3] + d1, 0.f) * w1;
        }
        s0 += __shfl_xor_sync(0xffffffffu, s0, 1);
        s0 += __shfl_xor_sync(0xffffffffu, s0, 2);
        s1 += __shfl_xor_sync(0xffffffffu, s1, 1);
        s1 += __shfl_xor_sync(0xffffffffu, s1, 2);
        if ((lane & 3) == 0) {
            int rl = wm * 32 + it * 16 + (lane >> 2);
            red[rl][wn] = s0;
            red[rl + 8][wn] = s1;
        }
    }
    __syncthreads();
    if (tid < 64) {
        float t = red[tid][0] + red[tid][1] + red[tid][2] + red[tid][3];
        int row = bm + tid;
        if (row < NE) Wout[row] = t;
    }
}

// ---------------- per-edge relu-hidden + segment sum of relu(h) -------------------
__global__ void edge_r_kernel(const int* __restrict__ SRC, const int* __restrict__ DST,
                              float* __restrict__ WE,
                              const float* __restrict__ U, const float* __restrict__ V,
                              float* __restrict__ S, int doS)
{
    long idx = (long)blockIdx.x * blockDim.x + threadIdx.x;
    long e = idx >> 5;
    int lane = (int)(idx & 31);
    if (e >= NE) return;
    int src = SRC[e];
    int dst = DST[e];
    const float4 u = *(const float4*)(U + (long)dst * HH + lane * 4);
    const float4 v = *(const float4*)(V + (long)src * HH + lane * 4);
    float4 w = *(float4*)(WE + e * HH + lane * 4);
    w.x = fmaxf(u.x + v.x + w.x, 0.f);
    w.y = fmaxf(u.y + v.y + w.y, 0.f);
    w.z = fmaxf(u.z + v.z + w.z, 0.f);
    w.w = fmaxf(u.w + v.w + w.w, 0.f);
    *(float4*)(WE + e * HH + lane * 4) = w;
    if (doS) {
        float* sp = S + (long)dst * HH + lane * 4;
        atomicAdd(sp + 0, w.x);
        atomicAdd(sp + 1, w.y);
        atomicAdd(sp + 2, w.z);
        atomicAdd(sp + 3, w.w);
    }
}

// ---------------- small per-layer prep: C = W2@aW1, D = b2@aW1 + ab1 --------------
__global__ void prep_kernel(const float* __restrict__ W2, const float* __restrict__ aW1,
                            const float* __restrict__ b2, const float* __restrict__ ab1,
                            float* __restrict__ C, float* __restrict__ D)
{
    int j = threadIdx.x;   // 0..255
    int k = blockIdx.x;    // 0..128
    if (k < 128) {
        float s = 0.f;
#pragma unroll 8
        for (int t = 0; t < 128; t++) s += W2[k * 128 + t] * aW1[t * 256 + j];
        C[k * 256 + j] = s;
    } else {
        float s = ab1[j];
#pragma unroll 8
        for (int t = 0; t < 128; t++) s += b2[t] * aW1[t * 256 + j];
        D[j] = s;
    }
}

// ---------------- degree / denom -------------------------------------------------
__global__ void deg_kernel(const int* __restrict__ DST, float* __restrict__ DEG)
{
    int e = blockIdx.x * blockDim.x + threadIdx.x;
    if (e < NE) atomicAdd(&DEG[DST[e]], 1.f);
}

__global__ void dinv_kernel(const float* __restrict__ DEG, float* __restrict__ DINV,
                            float* __restrict__ BM)
{
    int n = blockIdx.x * blockDim.x + threadIdx.x;
    if (n >= NN) return;
    float d = DEG[n];
    DINV[n] = 1.f / fmaxf(d, 1.f);
    BM[n] = (d > 0.f) ? 1.f : 0.f;
}

// ---------------- per-edge equivariant pos accumulation --------------------------
__global__ void pos_edge_kernel(const int* __restrict__ SRC, const int* __restrict__ DST,
                                const float* __restrict__ W,
                                const float* __restrict__ ab2, const float* __restrict__ POS,
                                float* __restrict__ PACC)
{
    int e = blockIdx.x * blockDim.x + threadIdx.x;
    if (e >= NE) return;
    int src = SRC[e], dst = DST[e];
    float w = W[e] + ab2[0];
    float rx = POS[src * 3 + 0] - POS[dst * 3 + 0];
    float ry = POS[src * 3 + 1] - POS[dst * 3 + 1];
    float rz = POS[src * 3 + 2] - POS[dst * 3 + 2];
    float dist = sqrtf(rx * rx + ry * ry + rz * rz);
    float s = w / dist;
    atomicAdd(&PACC[dst * 3 + 0], s * rx);
    atomicAdd(&PACC[dst * 3 + 1], s * ry);
    atomicAdd(&PACC[dst * 3 + 2], s * rz);
}

__global__ void pos_apply_kernel(float* __restrict__ POS, const float* __restrict__ PACC,
                                 const float* __restrict__ DINV, float* __restrict__ outp)
{
    int n = blockIdx.x * blockDim.x + threadIdx.x;
    if (n >= NN) return;
    float di = DINV[n];
#pragma unroll
    for (int i = 0; i < 3; i++) {
        float v = POS[n * 3 + i] + PACC[n * 3 + i] * di;
        POS[n * 3 + i] = v;
        if (outp) outp[n * 3 + i] = v;
    }
}

// ---------------- host ------------------------------------------------------------
extern "C" void kernel_launch(void* const* d_in, const int* in_sizes, int n_in,
                              void* d_out, int out_size)
{
    const float* x        = (const float*)d_in[0];
    const int*   ei32     = (const int*)d_in[1];
    const float* ea       = (const float*)d_in[2];
    const float* pos      = (const float*)d_in[3];
    const float* mW1      = (const float*)d_in[4];
    const float* mb1      = (const float*)d_in[5];
    const float* mW2      = (const float*)d_in[6];
    const float* mb2      = (const float*)d_in[7];
    const float* aW1      = (const float*)d_in[8];
    const float* ab1      = (const float*)d_in[9];
    const float* aW2      = (const float*)d_in[10];
    const float* ab2      = (const float*)d_in[11];
    const float* nW1      = (const float*)d_in[12];
    const float* nb1      = (const float*)d_in[13];
    const float* nW2      = (const float*)d_in[14];
    const float* nb2      = (const float*)d_in[15];
    float* outp = (float*)d_out;

    float *pU, *pV, *pWE, *pS, *pINTRA, *pHID, *pXA, *pXB, *pPOS, *pPACC, *pW;
    float *pDEG, *pDINV, *pBM, *pC, *pD;
    int *pSRC, *pDST;
    cudaGetSymbolAddress((void**)&pU, g_U);
    cudaGetSymbolAddress((void**)&pV, g_V);
    cudaGetSymbolAddress((void**)&pWE, g_WE);
    cudaGetSymbolAddress((void**)&pS, g_S);
    cudaGetSymbolAddress((void**)&pINTRA, g_INTRA);
    cudaGetSymbolAddress((void**)&pHID, g_HID);
    cudaGetSymbolAddress((void**)&pXA, g_XA);
    cudaGetSymbolAddress((void**)&pXB, g_XB);
    cudaGetSymbolAddress((void**)&pPOS, g_POS);
    cudaGetSymbolAddress((void**)&pPACC, g_POSACC);
    cudaGetSymbolAddress((void**)&pW, g_W);
    cudaGetSymbolAddress((void**)&pDEG, g_DEG);
    cudaGetSymbolAddress((void**)&pDINV, g_DINV);
    cudaGetSymbolAddress((void**)&pBM, g_BMASK);
    cudaGetSymbolAddress((void**)&pC, g_C);
    cudaGetSymbolAddress((void**)&pD, g_D);
    cudaGetSymbolAddress((void**)&pSRC, g_SRC);
    cudaGetSymbolAddress((void**)&pDST, g_DST);

    cudaMemcpyAsync(pPOS, pos, (size_t)NN * 3 * sizeof(float), cudaMemcpyDeviceToDevice);
    convert_idx<<<(NE + 255) / 256, 256>>>(ei32, pSRC, pDST);
    cudaMemsetAsync(pDEG, 0, (size_t)NN * sizeof(float));
    deg_kernel<<<(NE + 255) / 256, 256>>>(pDST, pDEG);
    dinv_kernel<<<(NN + 255) / 256, 256>>>(pDEG, pDINV, pBM);

    const float* xc = x;
    float* xn = pXA;

    for (int l = 0; l < 3; l++) {
        const int last = (l == 2);
        const float* mW1l = mW1 + (long)l * 384 * 128;
        const float* mb1l = mb1 + (long)l * 128;
        const float* mW2l = mW2 + (long)l * 128 * 128;
        const float* mb2l = mb2 + (long)l * 128;
        const float* aW1l = aW1 + (long)l * 128 * 256;
        const float* ab1l = ab1 + (long)l * 256;
        const float* aW2l = aW2 + (long)l * 256;
        const float* ab2l = ab2 + (long)l;
        const float* nW1l = nW1 + (long)l * 256 * 256;
        const float* nb1l = nb1 + (long)l * 256;
        const float* nW2l = nW2 + (long)l * 256 * 128;
        const float* nb2l = nb2 + (long)l * 128;

        if (!last) cudaMemsetAsync(pS, 0, (size_t)NN * HH * sizeof(float));
        cudaMemsetAsync(pPACC, 0, (size_t)NN * 3 * sizeof(float));

        prep_kernel<<<129, 256>>>(mW2l, aW1l, mb2l, ab1l, pC, pD);

        dim3 gN(1, (NN + 63) / 64);
        gemm_tf32<<<gN, 256>>>(xc, nullptr, mW1l, nullptr, pU, NN, 128, 128, 0, nullptr, nullptr);
        gemm_tf32<<<gN, 256>>>(xc, nullptr, mW1l + 128 * 128, nullptr, pV, NN, 128, 128, 0, nullptr, nullptr);

        dim3 gE(1, (NE + 63) / 64);
        gemm_tf32<<<gE, 256>>>(ea, nullptr, mW1l + 256 * 128, mb1l, pWE, NE, 128, 128, 0, nullptr, nullptr);

        edge_r_kernel<<<(int)(((long)NE * 32 + 255) / 256), 256>>>(pSRC, pDST, pWE, pU, pV, pS, last ? 0 : 1);

        edge_acc_tf32<<<(NE + 63) / 64, 256>>>(pWE, pC, pD, aW2l, pW);

        pos_edge_kernel<<<(NE + 255) / 256, 256>>>(pSRC, pDST, pW, ab2l, pPOS, pPACC);
        pos_apply_kernel<<<(NN + 255) / 256, 256>>>(pPOS, pPACC, pDINV, last ? outp : nullptr);

        if (!last) {
            gemm_tf32<<<gN, 256>>>(pS, nullptr, mW2l, mb2l, pINTRA, NN, 128, 128, 0, pDINV, pBM);
            dim3 gH(2, (NN + 63) / 64);
            gemm_tf32<<<gH, 256>>>(xc, pINTRA, nW1l, nb1l, pHID, NN, 256, 256, 1, nullptr, nullptr);
            gemm_tf32<<<gN, 256>>>(pHID, nullptr, nW2l, nb2l, xn, NN, 256, 128, 0, nullptr, nullptr);
            xc = xn;
            xn = (xn == pXA) ? pXB : pXA;
        }
    }
}

// round 8
// speedup vs baseline: 3.3107x; 3.3107x over previous
#include <cuda_runtime.h>
#include <cstdint>

#define NN 50000
#define NE 500000
#define HH 128

// ---------------- scratch (device globals; no cudaMalloc allowed) ----------------
__device__ float g_U[NN * HH];
__device__ float g_V[NN * HH];
__device__ float g_WE[(long)NE * HH];   // holds ea@W1c+b1, then overwritten with relu(h)
__device__ float g_S[NN * HH];          // segment sum of relu(h)
__device__ float g_INTRA[NN * HH];
__device__ float g_HID[NN * 2 * HH];
__device__ float g_XA[NN * HH];
__device__ float g_XB[NN * HH];
__device__ float g_POS[NN * 3];
__device__ float g_POSACC[NN * 3];
__device__ float g_W[NE];               // per-edge scalar w
__device__ float g_DEG[NN];
__device__ float g_DINV[NN];
__device__ float g_BMASK[NN];
__device__ float g_C[HH * 256];         // W2 @ aW1
__device__ float g_D[256];              // b2 @ aW1 + ab1
__device__ int   g_SRC[NE];
__device__ int   g_DST[NE];

// ---------------- mma helper (raw fp32 bits; tf32 HW truncates mantissa) ----------
__device__ __forceinline__ void mma8(float c[4],
                                     unsigned a0, unsigned a1, unsigned a2, unsigned a3,
                                     unsigned b0, unsigned b1) {
    asm("mma.sync.aligned.m16n8k8.row.col.f32.tf32.tf32.f32 "
        "{%0,%1,%2,%3},{%4,%5,%6,%7},{%8,%9},{%0,%1,%2,%3};"
        : "+f"(c[0]), "+f"(c[1]), "+f"(c[2]), "+f"(c[3])
        : "r"(a0), "r"(a1), "r"(a2), "r"(a3), "r"(b0), "r"(b1));
}

// -------- index normalization: handles harness storing edge_index as int32 OR int64
__global__ void convert_idx(const int* __restrict__ ei32, int* __restrict__ SRC,
                            int* __restrict__ DST)
{
    bool is64 = (ei32[1] == 0 && ei32[3] == 0 && ei32[5] == 0 && ei32[7] == 0);
    int e = blockIdx.x * blockDim.x + threadIdx.x;
    if (e >= NE) return;
    if (is64) {
        const long long* e64 = (const long long*)ei32;
        SRC[e] = (int)e64[e];
        DST[e] = (int)e64[NE + e];
    } else {
        SRC[e] = ei32[e];
        DST[e] = ei32[NE + e];
    }
}

// ---------------- tf32 GEMM: 128(M) x 128(N) block, 256 threads -------------------
// 8 warps as 4(M) x 2(N); warp tile 32x64; mma m16n8k8 (raw fp32 bits as tf32).
// Shared: A row-major [128][16] padded stride 20 (conflict-free LDS.32 fragments),
//         B row-major [16][128] padded stride 136 (stride%32==8, conflict-free).
// C[m,j] = (A_logical[m,:] @ B)[j]*rowscale[m] + bias[j]*rowmask[m]; optional relu.
// If A2 != null: logical A row = concat(A[m,0:128], A2[m,0:128]) (K must be 256).
#define SA_STR 20
#define SB_STR 136
__global__ void __launch_bounds__(256) gemm_tf32(
    const float* __restrict__ A, const float* __restrict__ A2,
    const float* __restrict__ B, const float* __restrict__ bias,
    float* __restrict__ Cout, int M, int K, int Ncols,
    int reluFlag, const float* __restrict__ rowscale, const float* __restrict__ rowmask)
{
    __shared__ unsigned sA[128 * SA_STR];
    __shared__ unsigned sB[16 * SB_STR];
    const int bm = blockIdx.y * 128;
    const int bn = blockIdx.x * 128;
    const int tid = threadIdx.x;
    const int lane = tid & 31;
    const int warp = tid >> 5;
    const int wm = warp >> 1;   // 0..3
    const int wn = warp & 1;    // 0..1

    // staging assignment
    const int arow = tid >> 1;          // 0..127
    const int ac0  = (tid & 1) << 3;    // 0 or 8
    const int brow = tid >> 5;          // 0..7 (and +8)
    const int bn4  = (tid & 31) << 2;   // 0..124

    float acc[2][8][4];
#pragma unroll
    for (int i = 0; i < 2; i++)
#pragma unroll
        for (int j = 0; j < 8; j++)
#pragma unroll
            for (int q = 0; q < 4; q++) acc[i][j][q] = 0.f;

    uint4 pa0, pa1, pb0, pb1;
    // prefetch tile 0
    {
        int grow = bm + arow;
        pa0 = make_uint4(0, 0, 0, 0); pa1 = make_uint4(0, 0, 0, 0);
        if (grow < M) {
            int gk = ac0;
            const float* s;
            if (A2) s = (gk < HH) ? (A + (long)grow * HH + gk) : (A2 + (long)grow * HH + gk - HH);
            else    s = A + (long)grow * K + gk;
            pa0 = *(const uint4*)s;
            pa1 = *(const uint4*)(s + 4);
        }
        pb0 = *(const uint4*)(B + (long)brow * Ncols + bn + bn4);
        pb1 = *(const uint4*)(B + (long)(brow + 8) * Ncols + bn + bn4);
    }

    for (int k0 = 0; k0 < K; k0 += 16) {
        *(uint4*)&sA[arow * SA_STR + ac0]     = pa0;
        *(uint4*)&sA[arow * SA_STR + ac0 + 4] = pa1;
        *(uint4*)&sB[brow * SB_STR + bn4]       = pb0;
        *(uint4*)&sB[(brow + 8) * SB_STR + bn4] = pb1;
        __syncthreads();

        int kn = k0 + 16;
        if (kn < K) {
            int grow = bm + arow;
            pa0 = make_uint4(0, 0, 0, 0); pa1 = make_uint4(0, 0, 0, 0);
            if (grow < M) {
                int gk = kn + ac0;
                const float* s;
                if (A2) s = (gk < HH) ? (A + (long)grow * HH + gk) : (A2 + (long)grow * HH + gk - HH);
                else    s = A + (long)grow * K + gk;
                pa0 = *(const uint4*)s;
                pa1 = *(const uint4*)(s + 4);
            }
            pb0 = *(const uint4*)(B + (long)(kn + brow) * Ncols + bn + bn4);
            pb1 = *(const uint4*)(B + (long)(kn + brow + 8) * Ncols + bn + bn4);
        }

#pragma unroll
        for (int ks = 0; ks < 2; ks++) {
            const int kk = ks * 8 + (lane & 3);
            unsigned a[2][4];
#pragma unroll
            for (int it = 0; it < 2; it++) {
                int rb = wm * 32 + it * 16 + (lane >> 2);
                a[it][0] = sA[rb * SA_STR + kk];
                a[it][1] = sA[(rb + 8) * SA_STR + kk];
                a[it][2] = sA[rb * SA_STR + kk + 4];
                a[it][3] = sA[(rb + 8) * SA_STR + kk + 4];
            }
#pragma unroll
            for (int jt = 0; jt < 8; jt++) {
                int nb = wn * 64 + jt * 8 + (lane >> 2);
                unsigned b0 = sB[kk * SB_STR + nb];
                unsigned b1 = sB[(kk + 4) * SB_STR + nb];
                mma8(acc[0][jt], a[0][0], a[0][1], a[0][2], a[0][3], b0, b1);
                mma8(acc[1][jt], a[1][0], a[1][1], a[1][2], a[1][3], b0, b1);
            }
        }
        __syncthreads();
    }

    // epilogue
#pragma unroll
    for (int it = 0; it < 2; it++) {
        int row0 = bm + wm * 32 + it * 16 + (lane >> 2);
#pragma unroll
        for (int h = 0; h < 2; h++) {
            int row = row0 + h * 8;
            if (row >= M) continue;
            float rs = rowscale ? rowscale[row] : 1.f;
            float rm = rowmask ? rowmask[row] : 1.f;
#pragma unroll
            for (int jt = 0; jt < 8; jt++) {
                int col = bn + wn * 64 + jt * 8 + ((lane & 3) << 1);
                float v0 = acc[it][jt][h * 2 + 0] * rs;
                float v1 = acc[it][jt][h * 2 + 1] * rs;
                if (bias) { v0 += bias[col] * rm; v1 += bias[col + 1] * rm; }
                if (reluFlag) { v0 = fmaxf(v0, 0.f); v1 = fmaxf(v1, 0.f); }
                *(float2*)(Cout + (long)row * Ncols + col) = make_float2(v0, v1);
            }
        }
    }
}

// -------- fused edge-acc GEMM (tf32): w[e] = sum_j relu(R[e]@C + D)[j]*aW2[j] -----
// Block: 64 edges x 256 cols, K=128. 8 warps as 2(M) x 4(N); warp tile 32x64.
#define SBE_STR 264
__global__ void __launch_bounds__(256) edge_acc_tf32(
    const float* __restrict__ R, const float* __restrict__ Cm,
    const float* __restrict__ D, const float* __restrict__ aW2,
    float* __restrict__ Wout)
{
    __shared__ unsigned sA[64 * SA_STR];
    __shared__ unsigned sB[16 * SBE_STR];
    __shared__ float red[64][4];
    const int bm = blockIdx.x * 64;
    const int tid = threadIdx.x;
    const int lane = tid & 31;
    const int warp = tid >> 5;
    const int wm = warp >> 2;   // 0..1
    const int wn = warp & 3;    // 0..3

    const int arow = tid >> 2;          // 0..63
    const int ac0  = (tid & 3) << 2;    // 0,4,8,12
    const int brow = tid >> 6;          // 0..3 (+4k per p)
    const int bn4  = (tid & 63) << 2;   // 0..252

    float acc[2][8][4];
#pragma unroll
    for (int i = 0; i < 2; i++)
#pragma unroll
        for (int j = 0; j < 8; j++)
#pragma unroll
            for (int q = 0; q < 4; q++) acc[i][j][q] = 0.f;

    uint4 pa, pb[4];
    {
        int grow = bm + arow;
        pa = make_uint4(0, 0, 0, 0);
        if (grow < NE) pa = *(const uint4*)(R + (long)grow * HH + ac0);
#pragma unroll
        for (int p = 0; p < 4; p++)
            pb[p] = *(const uint4*)(Cm + (long)(p * 4 + brow) * 256 + bn4);
    }

    for (int k0 = 0; k0 < 128; k0 += 16) {
        *(uint4*)&sA[arow * SA_STR + ac0] = pa;
#pragma unroll
        for (int p = 0; p < 4; p++)
            *(uint4*)&sB[(p * 4 + brow) * SBE_STR + bn4] = pb[p];
        __syncthreads();

        int kn = k0 + 16;
        if (kn < 128) {
            int grow = bm + arow;
            pa = make_uint4(0, 0, 0, 0);
            if (grow < NE) pa = *(const uint4*)(R + (long)grow * HH + kn + ac0);
#pragma unroll
            for (int p = 0; p < 4; p++)
                pb[p] = *(const uint4*)(Cm + (long)(kn + p * 4 + brow) * 256 + bn4);
        }

#pragma unroll
        for (int ks = 0; ks < 2; ks++) {
            const int kk = ks * 8 + (lane & 3);
            unsigned a[2][4];
#pragma unroll
            for (int it = 0; it < 2; it++) {
                int rb = wm * 32 + it * 16 + (lane >> 2);
                a[it][0] = sA[rb * SA_STR + kk];
                a[it][1] = sA[(rb + 8) * SA_STR + kk];
                a[it][2] = sA[rb * SA_STR + kk + 4];
                a[it][3] = sA[(rb + 8) * SA_STR + kk + 4];
            }
#pragma unroll
            for (int jt = 0; jt < 8; jt++) {
                int nb = wn * 64 + jt * 8 + (lane >> 2);
                unsigned b0 = sB[kk * SBE_STR + nb];
                unsigned b1 = sB[(kk + 4) * SBE_STR + nb];
                mma8(acc[0][jt], a[0][0], a[0][1], a[0][2], a[0][3], b0, b1);
                mma8(acc[1][jt], a[1][0], a[1][1], a[1][2], a[1][3], b0, b1);
            }
        }
        __syncthreads();
    }

    // epilogue: relu(acc + D)*aW2, reduce across 256 cols
#pragma unroll
    for (int it = 0; it < 2; it++) {
        float s0 = 0.f, s1 = 0.f;
#pragma unroll
        for (int jt = 0; jt < 8; jt++) {
            int col = wn * 64 + jt * 8 + ((lane & 3) << 1);
            float d0 = D[col], d1 = D[col + 1];
            float w0 = aW2[col], w1 = aW2[col + 1];
            s0 += fmaxf(acc[it][jt][0] + d0, 0.f) * w0 + fmaxf(acc[it][jt][1] + d1, 0.f) * w1;
            s1 += fmaxf(acc[it][jt][2] + d0, 0.f) * w0 + fmaxf(acc[it][jt][3] + d1, 0.f) * w1;
        }
        s0 += __shfl_xor_sync(0xffffffffu, s0, 1);
        s0 += __shfl_xor_sync(0xffffffffu, s0, 2);
        s1 += __shfl_xor_sync(0xffffffffu, s1, 1);
        s1 += __shfl_xor_sync(0xffffffffu, s1, 2);
        if ((lane & 3) == 0) {
            int rl = wm * 32 + it * 16 + (lane >> 2);
            red[rl][wn] = s0;
            red[rl + 8][wn] = s1;
        }
    }
    __syncthreads();
    if (tid < 64) {
        float t = red[tid][0] + red[tid][1] + red[tid][2] + red[tid][3];
        int row = bm + tid;
        if (row < NE) Wout[row] = t;
    }
}

// ---------------- per-edge relu-hidden + segment sum of relu(h) -------------------
__global__ void edge_r_kernel(const int* __restrict__ SRC, const int* __restrict__ DST,
                              float* __restrict__ WE,
                              const float* __restrict__ U, const float* __restrict__ V,
                              float* __restrict__ S, int doS)
{
    long idx = (long)blockIdx.x * blockDim.x + threadIdx.x;
    long e = idx >> 5;
    int lane = (int)(idx & 31);
    if (e >= NE) return;
    int src = SRC[e];
    int dst = DST[e];
    const float4 u = *(const float4*)(U + (long)dst * HH + lane * 4);
    const float4 v = *(const float4*)(V + (long)src * HH + lane * 4);
    float4 w = *(float4*)(WE + e * HH + lane * 4);
    w.x = fmaxf(u.x + v.x + w.x, 0.f);
    w.y = fmaxf(u.y + v.y + w.y, 0.f);
    w.z = fmaxf(u.z + v.z + w.z, 0.f);
    w.w = fmaxf(u.w + v.w + w.w, 0.f);
    *(float4*)(WE + e * HH + lane * 4) = w;
    if (doS) {
        float* sp = S + (long)dst * HH + lane * 4;
        atomicAdd(sp + 0, w.x);
        atomicAdd(sp + 1, w.y);
        atomicAdd(sp + 2, w.z);
        atomicAdd(sp + 3, w.w);
    }
}

// ---------------- small per-layer prep: C = W2@aW1, D = b2@aW1 + ab1 --------------
__global__ void prep_kernel(const float* __restrict__ W2, const float* __restrict__ aW1,
                            const float* __restrict__ b2, const float* __restrict__ ab1,
                            float* __restrict__ C, float* __restrict__ D)
{
    int j = threadIdx.x;   // 0..255
    int k = blockIdx.x;    // 0..128
    if (k < 128) {
        float s = 0.f;
#pragma unroll 8
        for (int t = 0; t < 128; t++) s += W2[k * 128 + t] * aW1[t * 256 + j];
        C[k * 256 + j] = s;
    } else {
        float s = ab1[j];
#pragma unroll 8
        for (int t = 0; t < 128; t++) s += b2[t] * aW1[t * 256 + j];
        D[j] = s;
    }
}

// ---------------- degree / denom -------------------------------------------------
__global__ void deg_kernel(const int* __restrict__ DST, float* __restrict__ DEG)
{
    int e = blockIdx.x * blockDim.x + threadIdx.x;
    if (e < NE) atomicAdd(&DEG[DST[e]], 1.f);
}

__global__ void dinv_kernel(const float* __restrict__ DEG, float* __restrict__ DINV,
                            float* __restrict__ BM)
{
    int n = blockIdx.x * blockDim.x + threadIdx.x;
    if (n >= NN) return;
    float d = DEG[n];
    DINV[n] = 1.f / fmaxf(d, 1.f);
    BM[n] = (d > 0.f) ? 1.f : 0.f;
}

// ---------------- per-edge equivariant pos accumulation --------------------------
__global__ void pos_edge_kernel(const int* __restrict__ SRC, const int* __restrict__ DST,
                                const float* __restrict__ W,
                                const float* __restrict__ ab2, const float* __restrict__ POS,
                                float* __restrict__ PACC)
{
    int e = blockIdx.x * blockDim.x + threadIdx.x;
    if (e >= NE) return;
    int src = SRC[e], dst = DST[e];
    float w = W[e] + ab2[0];
    float rx = POS[src * 3 + 0] - POS[dst * 3 + 0];
    float ry = POS[src * 3 + 1] - POS[dst * 3 + 1];
    float rz = POS[src * 3 + 2] - POS[dst * 3 + 2];
    float dist = sqrtf(rx * rx + ry * ry + rz * rz);
    float s = w / dist;
    atomicAdd(&PACC[dst * 3 + 0], s * rx);
    atomicAdd(&PACC[dst * 3 + 1], s * ry);
    atomicAdd(&PACC[dst * 3 + 2], s * rz);
}

__global__ void pos_apply_kernel(float* __restrict__ POS, const float* __restrict__ PACC,
                                 const float* __restrict__ DINV, float* __restrict__ outp)
{
    int n = blockIdx.x * blockDim.x + threadIdx.x;
    if (n >= NN) return;
    float di = DINV[n];
#pragma unroll
    for (int i = 0; i < 3; i++) {
        float v = POS[n * 3 + i] + PACC[n * 3 + i] * di;
        POS[n * 3 + i] = v;
        if (outp) outp[n * 3 + i] = v;
    }
}

// ---------------- host ------------------------------------------------------------
extern "C" void kernel_launch(void* const* d_in, const int* in_sizes, int n_in,
                              void* d_out, int out_size)
{
    const float* x        = (const float*)d_in[0];
    const int*   ei32     = (const int*)d_in[1];
    const float* ea       = (const float*)d_in[2];
    const float* pos      = (const float*)d_in[3];
    const float* mW1      = (const float*)d_in[4];
    const float* mb1      = (const float*)d_in[5];
    const float* mW2      = (const float*)d_in[6];
    const float* mb2      = (const float*)d_in[7];
    const float* aW1      = (const float*)d_in[8];
    const float* ab1      = (const float*)d_in[9];
    const float* aW2      = (const float*)d_in[10];
    const float* ab2      = (const float*)d_in[11];
    const float* nW1      = (const float*)d_in[12];
    const float* nb1      = (const float*)d_in[13];
    const float* nW2      = (const float*)d_in[14];
    const float* nb2      = (const float*)d_in[15];
    float* outp = (float*)d_out;

    float *pU, *pV, *pWE, *pS, *pINTRA, *pHID, *pXA, *pXB, *pPOS, *pPACC, *pW;
    float *pDEG, *pDINV, *pBM, *pC, *pD;
    int *pSRC, *pDST;
    cudaGetSymbolAddress((void**)&pU, g_U);
    cudaGetSymbolAddress((void**)&pV, g_V);
    cudaGetSymbolAddress((void**)&pWE, g_WE);
    cudaGetSymbolAddress((void**)&pS, g_S);
    cudaGetSymbolAddress((void**)&pINTRA, g_INTRA);
    cudaGetSymbolAddress((void**)&pHID, g_HID);
    cudaGetSymbolAddress((void**)&pXA, g_XA);
    cudaGetSymbolAddress((void**)&pXB, g_XB);
    cudaGetSymbolAddress((void**)&pPOS, g_POS);
    cudaGetSymbolAddress((void**)&pPACC, g_POSACC);
    cudaGetSymbolAddress((void**)&pW, g_W);
    cudaGetSymbolAddress((void**)&pDEG, g_DEG);
    cudaGetSymbolAddress((void**)&pDINV, g_DINV);
    cudaGetSymbolAddress((void**)&pBM, g_BMASK);
    cudaGetSymbolAddress((void**)&pC, g_C);
    cudaGetSymbolAddress((void**)&pD, g_D);
    cudaGetSymbolAddress((void**)&pSRC, g_SRC);
    cudaGetSymbolAddress((void**)&pDST, g_DST);

    cudaMemcpyAsync(pPOS, pos, (size_t)NN * 3 * sizeof(float), cudaMemcpyDeviceToDevice);
    convert_idx<<<(NE + 255) / 256, 256>>>(ei32, pSRC, pDST);
    cudaMemsetAsync(pDEG, 0, (size_t)NN * sizeof(float));
    deg_kernel<<<(NE + 255) / 256, 256>>>(pDST, pDEG);
    dinv_kernel<<<(NN + 255) / 256, 256>>>(pDEG, pDINV, pBM);

    const float* xc = x;
    float* xn = pXA;

    for (int l = 0; l < 3; l++) {
        const int last = (l == 2);
        const float* mW1l = mW1 + (long)l * 384 * 128;
        const float* mb1l = mb1 + (long)l * 128;
        const float* mW2l = mW2 + (long)l * 128 * 128;
        const float* mb2l = mb2 + (long)l * 128;
        const float* aW1l = aW1 + (long)l * 128 * 256;
        const float* ab1l = ab1 + (long)l * 256;
        const float* aW2l = aW2 + (long)l * 256;
        const float* ab2l = ab2 + (long)l;
        const float* nW1l = nW1 + (long)l * 256 * 256;
        const float* nb1l = nb1 + (long)l * 256;
        const float* nW2l = nW2 + (long)l * 256 * 128;
        const float* nb2l = nb2 + (long)l * 128;

        if (!last) cudaMemsetAsync(pS, 0, (size_t)NN * HH * sizeof(float));
        cudaMemsetAsync(pPACC, 0, (size_t)NN * 3 * sizeof(float));

        prep_kernel<<<129, 256>>>(mW2l, aW1l, mb2l, ab1l, pC, pD);

        dim3 gN(1, (NN + 127) / 128);
        gemm_tf32<<<gN, 256>>>(xc, nullptr, mW1l, nullptr, pU, NN, 128, 128, 0, nullptr, nullptr);
        gemm_tf32<<<gN, 256>>>(xc, nullptr, mW1l + 128 * 128, nullptr, pV, NN, 128, 128, 0, nullptr, nullptr);

        dim3 gE(1, (NE + 127) / 128);
        gemm_tf32<<<gE, 256>>>(ea, nullptr, mW1l + 256 * 128, mb1l, pWE, NE, 128, 128, 0, nullptr, nullptr);

        edge_r_kernel<<<(int)(((long)NE * 32 + 255) / 256), 256>>>(pSRC, pDST, pWE, pU, pV, pS, last ? 0 : 1);

        edge_acc_tf32<<<(NE + 63) / 64, 256>>>(pWE, pC, pD, aW2l, pW);

        pos_edge_kernel<<<(NE + 255) / 256, 256>>>(pSRC, pDST, pW, ab2l, pPOS, pPACC);
        pos_apply_kernel<<<(NN + 255) / 256, 256>>>(pPOS, pPACC, pDINV, last ? outp : nullptr);

        if (!last) {
            gemm_tf32<<<gN, 256>>>(pS, nullptr, mW2l, mb2l, pINTRA, NN, 128, 128, 0, pDINV, pBM);
            dim3 gH(2, (NN + 127) / 128);
            gemm_tf32<<<gH, 256>>>(xc, pINTRA, nW1l, nb1l, pHID, NN, 256, 256, 1, nullptr, nullptr);
            gemm_tf32<<<gN, 256>>>(pHID, nullptr, nW2l, nb2l, xn, NN, 256, 128, 0, nullptr, nullptr);
            xc = xn;
            xn = (xn == pXA) ? pXB : pXA;
        }
    }
}

// round 9
// speedup vs baseline: 3.6529x; 1.1034x over previous
#include <cuda_runtime.h>
#include <cstdint>

#define NN 50000
#define NE 500000
#define HH 128

// ---------------- scratch (device globals; no cudaMalloc allowed) ----------------
__device__ float g_U[NN * HH];
__device__ float g_V[NN * HH];
__device__ float g_S[NN * HH];          // segment sum of relu(h)
__device__ float g_INTRA[NN * HH];
__device__ float g_HID[NN * 2 * HH];
__device__ float g_XA[NN * HH];
__device__ float g_XB[NN * HH];
__device__ float g_POS[NN * 3];
__device__ float g_POSACC[NN * 3];
__device__ float g_W[NE];               // per-edge scalar w
__device__ float g_DEG[NN];
__device__ float g_DINV[NN];
__device__ float g_BMASK[NN];
__device__ float g_C[HH * 256];         // W2 @ aW1
__device__ float g_D[256];              // b2 @ aW1 + ab1
__device__ int   g_SRC[NE];
__device__ int   g_DST[NE];

// ---------------- mma helper (raw fp32 bits; tf32 HW truncates mantissa) ----------
__device__ __forceinline__ void mma8(float c[4],
                                     unsigned a0, unsigned a1, unsigned a2, unsigned a3,
                                     unsigned b0, unsigned b1) {
    asm("mma.sync.aligned.m16n8k8.row.col.f32.tf32.tf32.f32 "
        "{%0,%1,%2,%3},{%4,%5,%6,%7},{%8,%9},{%0,%1,%2,%3};"
        : "+f"(c[0]), "+f"(c[1]), "+f"(c[2]), "+f"(c[3])
        : "r"(a0), "r"(a1), "r"(a2), "r"(a3), "r"(b0), "r"(b1));
}

// -------- index normalization: handles harness storing edge_index as int32 OR int64
__global__ void convert_idx(const int* __restrict__ ei32, int* __restrict__ SRC,
                            int* __restrict__ DST)
{
    bool is64 = (ei32[1] == 0 && ei32[3] == 0 && ei32[5] == 0 && ei32[7] == 0);
    int e = blockIdx.x * blockDim.x + threadIdx.x;
    if (e >= NE) return;
    if (is64) {
        const long long* e64 = (const long long*)ei32;
        SRC[e] = (int)e64[e];
        DST[e] = (int)e64[NE + e];
    } else {
        SRC[e] = ei32[e];
        DST[e] = ei32[NE + e];
    }
}

// ---------------- tf32 GEMM: 128(M) x 128(N) block, 256 threads (node side) -------
#define SA_STR 20
#define SB_STR 136
__global__ void __launch_bounds__(256) gemm_tf32(
    const float* __restrict__ A, const float* __restrict__ A2,
    const float* __restrict__ B, const float* __restrict__ bias,
    float* __restrict__ Cout, int M, int K, int Ncols,
    int reluFlag, const float* __restrict__ rowscale, const float* __restrict__ rowmask)
{
    __shared__ unsigned sA[128 * SA_STR];
    __shared__ unsigned sB[16 * SB_STR];
    const int bm = blockIdx.y * 128;
    const int bn = blockIdx.x * 128;
    const int tid = threadIdx.x;
    const int lane = tid & 31;
    const int warp = tid >> 5;
    const int wm = warp >> 1;   // 0..3
    const int wn = warp & 1;    // 0..1

    const int arow = tid >> 1;
    const int ac0  = (tid & 1) << 3;
    const int brow = tid >> 5;
    const int bn4  = (tid & 31) << 2;

    float acc[2][8][4];
#pragma unroll
    for (int i = 0; i < 2; i++)
#pragma unroll
        for (int j = 0; j < 8; j++)
#pragma unroll
            for (int q = 0; q < 4; q++) acc[i][j][q] = 0.f;

    uint4 pa0, pa1, pb0, pb1;
    {
        int grow = bm + arow;
        pa0 = make_uint4(0, 0, 0, 0); pa1 = make_uint4(0, 0, 0, 0);
        if (grow < M) {
            int gk = ac0;
            const float* s;
            if (A2) s = (gk < HH) ? (A + (long)grow * HH + gk) : (A2 + (long)grow * HH + gk - HH);
            else    s = A + (long)grow * K + gk;
            pa0 = *(const uint4*)s;
            pa1 = *(const uint4*)(s + 4);
        }
        pb0 = *(const uint4*)(B + (long)brow * Ncols + bn + bn4);
        pb1 = *(const uint4*)(B + (long)(brow + 8) * Ncols + bn + bn4);
    }

    for (int k0 = 0; k0 < K; k0 += 16) {
        *(uint4*)&sA[arow * SA_STR + ac0]     = pa0;
        *(uint4*)&sA[arow * SA_STR + ac0 + 4] = pa1;
        *(uint4*)&sB[brow * SB_STR + bn4]       = pb0;
        *(uint4*)&sB[(brow + 8) * SB_STR + bn4] = pb1;
        __syncthreads();

        int kn = k0 + 16;
        if (kn < K) {
            int grow = bm + arow;
            pa0 = make_uint4(0, 0, 0, 0); pa1 = make_uint4(0, 0, 0, 0);
            if (grow < M) {
                int gk = kn + ac0;
                const float* s;
                if (A2) s = (gk < HH) ? (A + (long)grow * HH + gk) : (A2 + (long)grow * HH + gk - HH);
                else    s = A + (long)grow * K + gk;
                pa0 = *(const uint4*)s;
                pa1 = *(const uint4*)(s + 4);
            }
            pb0 = *(const uint4*)(B + (long)(kn + brow) * Ncols + bn + bn4);
            pb1 = *(const uint4*)(B + (long)(kn + brow + 8) * Ncols + bn + bn4);
        }

#pragma unroll
        for (int ks = 0; ks < 2; ks++) {
            const int kk = ks * 8 + (lane & 3);
            unsigned a[2][4];
#pragma unroll
            for (int it = 0; it < 2; it++) {
                int rb = wm * 32 + it * 16 + (lane >> 2);
                a[it][0] = sA[rb * SA_STR + kk];
                a[it][1] = sA[(rb + 8) * SA_STR + kk];
                a[it][2] = sA[rb * SA_STR + kk + 4];
                a[it][3] = sA[(rb + 8) * SA_STR + kk + 4];
            }
#pragma unroll
            for (int jt = 0; jt < 8; jt++) {
                int nb = wn * 64 + jt * 8 + (lane >> 2);
                unsigned b0 = sB[kk * SB_STR + nb];
                unsigned b1 = sB[(kk + 4) * SB_STR + nb];
                mma8(acc[0][jt], a[0][0], a[0][1], a[0][2], a[0][3], b0, b1);
                mma8(acc[1][jt], a[1][0], a[1][1], a[1][2], a[1][3], b0, b1);
            }
        }
        __syncthreads();
    }

#pragma unroll
    for (int it = 0; it < 2; it++) {
        int row0 = bm + wm * 32 + it * 16 + (lane >> 2);
#pragma unroll
        for (int h = 0; h < 2; h++) {
            int row = row0 + h * 8;
            if (row >= M) continue;
            float rs = rowscale ? rowscale[row] : 1.f;
            float rm = rowmask ? rowmask[row] : 1.f;
#pragma unroll
            for (int jt = 0; jt < 8; jt++) {
                int col = bn + wn * 64 + jt * 8 + ((lane & 3) << 1);
                float v0 = acc[it][jt][h * 2 + 0] * rs;
                float v1 = acc[it][jt][h * 2 + 1] * rs;
                if (bias) { v0 += bias[col] * rm; v1 += bias[col + 1] * rm; }
                if (reluFlag) { v0 = fmaxf(v0, 0.f); v1 = fmaxf(v1, 0.f); }
                *(float2*)(Cout + (long)row * Ncols + col) = make_float2(v0, v1);
            }
        }
    }
}

// ---------------- FUSED edge kernel ------------------------------------------------
// Per block (64 edges):
//  phase 1: H = ea@W1c (tf32 GEMM, K=128) + b1 + U[dst] + V[src], relu -> shared sH
//  phase 1b: S[dst] += relu(h) via red.global.add.v4.f32 (if doS)
//  phase 2: w[e] = sum_j relu(H@C + D)[j] * aW2[j] (tf32 GEMM from sH, 256 cols)
// Dynamic shared layout (bytes):
//  sH   @ 0      : 64*132*4 = 33792  (stride 132 -> conflict-free LDS.32 fragments)
//  sAe  @ 33792  : 64*20*4  = 5120   (phase-1 A staging)
//  sB1  @ 38912  : 16*136*4 = 8704   (phase-1 B staging)
//  sB2  @ 33792  : 16*264*4 = 16896  (phase-2 B staging; reuses phase-1 region)
//  sDst @ 50688, sSrc @ 50944, red @ 51200 (64*4 floats)   total 52224
#define SH_STR 132
#define SB2_STR 264
__global__ void __launch_bounds__(256) fused_edge(
    const float* __restrict__ EA, const float* __restrict__ W1c,
    const float* __restrict__ b1,
    const float* __restrict__ U, const float* __restrict__ V,
    const int* __restrict__ SRC, const int* __restrict__ DST,
    const float* __restrict__ Cm, const float* __restrict__ D,
    const float* __restrict__ aW2,
    float* __restrict__ S, float* __restrict__ Wout, int doS)
{
    extern __shared__ char smem[];
    float*    sH  = (float*)smem;
    unsigned* sAe = (unsigned*)(smem + 33792);
    unsigned* sB1 = (unsigned*)(smem + 38912);
    unsigned* sB2 = (unsigned*)(smem + 33792);
    int*   sDst = (int*)(smem + 50688);
    int*   sSrc = (int*)(smem + 50944);
    float (*red)[4] = (float(*)[4])(smem + 51200);

    const int bm = blockIdx.x * 64;
    const int tid = threadIdx.x;
    const int lane = tid & 31;
    const int warp = tid >> 5;
    const int wm = warp >> 2;   // 0..1
    const int wn = warp & 3;    // 0..3

    // phase 0: stage edge indices
    if (tid < 64) {
        int e = bm + tid;
        sDst[tid] = (e < NE) ? DST[e] : 0;
        sSrc[tid] = (e < NE) ? SRC[e] : 0;
    }

    // ---------------- phase 1: GEMM ea @ W1c (64 x 128, K=128) ----------------
    const int arow = tid >> 2;          // 0..63
    const int ac0  = (tid & 3) << 2;    // 0,4,8,12
    const int brow = tid >> 5;          // 0..7 (+8)
    const int bn4  = (tid & 31) << 2;   // 0..124

    {
        float acc[2][4][4];
#pragma unroll
        for (int i = 0; i < 2; i++)
#pragma unroll
            for (int j = 0; j < 4; j++)
#pragma unroll
                for (int q = 0; q < 4; q++) acc[i][j][q] = 0.f;

        uint4 pa, pb0, pb1;
        {
            int grow = bm + arow;
            pa = make_uint4(0, 0, 0, 0);
            if (grow < NE) pa = *(const uint4*)(EA + (long)grow * HH + ac0);
            pb0 = *(const uint4*)(W1c + (long)brow * HH + bn4);
            pb1 = *(const uint4*)(W1c + (long)(brow + 8) * HH + bn4);
        }

        for (int k0 = 0; k0 < 128; k0 += 16) {
            *(uint4*)&sAe[arow * SA_STR + ac0] = pa;
            *(uint4*)&sB1[brow * SB_STR + bn4] = pb0;
            *(uint4*)&sB1[(brow + 8) * SB_STR + bn4] = pb1;
            __syncthreads();

            int kn = k0 + 16;
            if (kn < 128) {
                int grow = bm + arow;
                pa = make_uint4(0, 0, 0, 0);
                if (grow < NE) pa = *(const uint4*)(EA + (long)grow * HH + kn + ac0);
                pb0 = *(const uint4*)(W1c + (long)(kn + brow) * HH + bn4);
                pb1 = *(const uint4*)(W1c + (long)(kn + brow + 8) * HH + bn4);
            }

#pragma unroll
            for (int ks = 0; ks < 2; ks++) {
                const int kk = ks * 8 + (lane & 3);
                unsigned a[2][4];
#pragma unroll
                for (int it = 0; it < 2; it++) {
                    int rb = wm * 32 + it * 16 + (lane >> 2);
                    a[it][0] = sAe[rb * SA_STR + kk];
                    a[it][1] = sAe[(rb + 8) * SA_STR + kk];
                    a[it][2] = sAe[rb * SA_STR + kk + 4];
                    a[it][3] = sAe[(rb + 8) * SA_STR + kk + 4];
                }
#pragma unroll
                for (int jt = 0; jt < 4; jt++) {
                    int nb = wn * 32 + jt * 8 + (lane >> 2);
                    unsigned b0 = sB1[kk * SB_STR + nb];
                    unsigned b1r = sB1[(kk + 4) * SB_STR + nb];
                    mma8(acc[0][jt], a[0][0], a[0][1], a[0][2], a[0][3], b0, b1r);
                    mma8(acc[1][jt], a[1][0], a[1][1], a[1][2], a[1][3], b0, b1r);
                }
            }
            __syncthreads();
        }

        // epilogue: + b1 + U[dst] + V[src], relu, -> sH
#pragma unroll
        for (int it = 0; it < 2; it++) {
#pragma unroll
            for (int h = 0; h < 2; h++) {
                int r = wm * 32 + it * 16 + (lane >> 2) + h * 8;
                bool valid = (bm + r) < NE;
                int d = sDst[r], s = sSrc[r];
#pragma unroll
                for (int jt = 0; jt < 4; jt++) {
                    int c = wn * 32 + jt * 8 + ((lane & 3) << 1);
                    float v0 = 0.f, v1 = 0.f;
                    if (valid) {
                        float2 uu = *(const float2*)(U + (long)d * HH + c);
                        float2 vv = *(const float2*)(V + (long)s * HH + c);
                        v0 = fmaxf(acc[it][jt][h * 2 + 0] + b1[c]     + uu.x + vv.x, 0.f);
                        v1 = fmaxf(acc[it][jt][h * 2 + 1] + b1[c + 1] + uu.y + vv.y, 0.f);
                    }
                    *(float2*)&sH[r * SH_STR + c] = make_float2(v0, v1);
                }
            }
        }
    }
    __syncthreads();

    // ---------------- phase 1b: S[dst] += relu(h) (vector red) ----------------
    if (doS) {
        int r = tid >> 2;
        int c4 = tid & 3;
        if (bm + r < NE) {
            float* base = S + (long)sDst[r] * HH;
#pragma unroll
            for (int p = 0; p < 8; p++) {
                int ci = (c4 * 8 + p) * 4;
                float4 v = *(const float4*)&sH[r * SH_STR + ci];
                if (v.x != 0.f || v.y != 0.f || v.z != 0.f || v.w != 0.f) {
                    asm volatile("red.global.add.v4.f32 [%0], {%1,%2,%3,%4};"
                                 :: "l"(base + ci), "f"(v.x), "f"(v.y), "f"(v.z), "f"(v.w)
                                 : "memory");
                }
            }
        }
    }

    // ---------------- phase 2: w[e] = sum_j relu(H@C + D)[j]*aW2[j] ----------------
    {
        const int brow2 = tid >> 6;         // 0..3
        const int bn4b  = (tid & 63) << 2;  // 0..252

        float acc2[2][8][4];
#pragma unroll
        for (int i = 0; i < 2; i++)
#pragma unroll
            for (int j = 0; j < 8; j++)
#pragma unroll
                for (int q = 0; q < 4; q++) acc2[i][j][q] = 0.f;

        uint4 pb[4];
#pragma unroll
        for (int p = 0; p < 4; p++)
            pb[p] = *(const uint4*)(Cm + (long)(p * 4 + brow2) * 256 + bn4b);

        for (int k0 = 0; k0 < 128; k0 += 16) {
            __syncthreads();   // protect sB2 (and first iter: sH complete from all warps)
#pragma unroll
            for (int p = 0; p < 4; p++)
                *(uint4*)&sB2[(p * 4 + brow2) * SB2_STR + bn4b] = pb[p];
            __syncthreads();

            int kn = k0 + 16;
            if (kn < 128) {
#pragma unroll
                for (int p = 0; p < 4; p++)
                    pb[p] = *(const uint4*)(Cm + (long)(kn + p * 4 + brow2) * 256 + bn4b);
            }

#pragma unroll
            for (int ks = 0; ks < 2; ks++) {
                const int kkl = ks * 8 + (lane & 3);
                const int kkg = k0 + kkl;
                unsigned a[2][4];
#pragma unroll
                for (int it = 0; it < 2; it++) {
                    int rb = wm * 32 + it * 16 + (lane >> 2);
                    a[it][0] = __float_as_uint(sH[rb * SH_STR + kkg]);
                    a[it][1] = __float_as_uint(sH[(rb + 8) * SH_STR + kkg]);
                    a[it][2] = __float_as_uint(sH[rb * SH_STR + kkg + 4]);
                    a[it][3] = __float_as_uint(sH[(rb + 8) * SH_STR + kkg + 4]);
                }
#pragma unroll
                for (int jt = 0; jt < 8; jt++) {
                    int nb = wn * 64 + jt * 8 + (lane >> 2);
                    unsigned b0 = sB2[kkl * SB2_STR + nb];
                    unsigned b1r = sB2[(kkl + 4) * SB2_STR + nb];
                    mma8(acc2[0][jt], a[0][0], a[0][1], a[0][2], a[0][3], b0, b1r);
                    mma8(acc2[1][jt], a[1][0], a[1][1], a[1][2], a[1][3], b0, b1r);
                }
            }
        }
        __syncthreads();

        // epilogue: relu(acc2 + D)*aW2, reduce across 256 cols
#pragma unroll
        for (int it = 0; it < 2; it++) {
            float s0 = 0.f, s1 = 0.f;
#pragma unroll
            for (int jt = 0; jt < 8; jt++) {
                int col = wn * 64 + jt * 8 + ((lane & 3) << 1);
                float d0 = D[col], d1 = D[col + 1];
                float w0 = aW2[col], w1 = aW2[col + 1];
                s0 += fmaxf(acc2[it][jt][0] + d0, 0.f) * w0 + fmaxf(acc2[it][jt][1] + d1, 0.f) * w1;
                s1 += fmaxf(acc2[it][jt][2] + d0, 0.f) * w0 + fmaxf(acc2[it][jt][3] + d1, 0.f) * w1;
            }
            s0 += __shfl_xor_sync(0xffffffffu, s0, 1);
            s0 += __shfl_xor_sync(0xffffffffu, s0, 2);
            s1 += __shfl_xor_sync(0xffffffffu, s1, 1);
            s1 += __shfl_xor_sync(0xffffffffu, s1, 2);
            if ((lane & 3) == 0) {
                int rl = wm * 32 + it * 16 + (lane >> 2);
                red[rl][wn] = s0;
                red[rl + 8][wn] = s1;
            }
        }
        __syncthreads();
        if (tid < 64) {
            float t = red[tid][0] + red[tid][1] + red[tid][2] + red[tid][3];
            int row = bm + tid;
            if (row < NE) Wout[row] = t;
        }
    }
}

// ---------------- small per-layer prep: C = W2@aW1, D = b2@aW1 + ab1 --------------
__global__ void prep_kernel(const float* __restrict__ W2, const float* __restrict__ aW1,
                            const float* __restrict__ b2, const float* __restrict__ ab1,
                            float* __restrict__ C, float* __restrict__ D)
{
    int j = threadIdx.x;   // 0..255
    int k = blockIdx.x;    // 0..128
    if (k < 128) {
        float s = 0.f;
#pragma unroll 8
        for (int t = 0; t < 128; t++) s += W2[k * 128 + t] * aW1[t * 256 + j];
        C[k * 256 + j] = s;
    } else {
        float s = ab1[j];
#pragma unroll 8
        for (int t = 0; t < 128; t++) s += b2[t] * aW1[t * 256 + j];
        D[j] = s;
    }
}

// ---------------- degree / denom -------------------------------------------------
__global__ void deg_kernel(const int* __restrict__ DST, float* __restrict__ DEG)
{
    int e = blockIdx.x * blockDim.x + threadIdx.x;
    if (e < NE) atomicAdd(&DEG[DST[e]], 1.f);
}

__global__ void dinv_kernel(const float* __restrict__ DEG, float* __restrict__ DINV,
                            float* __restrict__ BM)
{
    int n = blockIdx.x * blockDim.x + threadIdx.x;
    if (n >= NN) return;
    float d = DEG[n];
    DINV[n] = 1.f / fmaxf(d, 1.f);
    BM[n] = (d > 0.f) ? 1.f : 0.f;
}

// ---------------- per-edge equivariant pos accumulation --------------------------
__global__ void pos_edge_kernel(const int* __restrict__ SRC, const int* __restrict__ DST,
                                const float* __restrict__ W,
                                const float* __restrict__ ab2, const float* __restrict__ POS,
                                float* __restrict__ PACC)
{
    int e = blockIdx.x * blockDim.x + threadIdx.x;
    if (e >= NE) return;
    int src = SRC[e], dst = DST[e];
    float w = W[e] + ab2[0];
    float rx = POS[src * 3 + 0] - POS[dst * 3 + 0];
    float ry = POS[src * 3 + 1] - POS[dst * 3 + 1];
    float rz = POS[src * 3 + 2] - POS[dst * 3 + 2];
    float dist = sqrtf(rx * rx + ry * ry + rz * rz);
    float s = w / dist;
    atomicAdd(&PACC[dst * 3 + 0], s * rx);
    atomicAdd(&PACC[dst * 3 + 1], s * ry);
    atomicAdd(&PACC[dst * 3 + 2], s * rz);
}

__global__ void pos_apply_kernel(float* __restrict__ POS, const float* __restrict__ PACC,
                                 const float* __restrict__ DINV, float* __restrict__ outp)
{
    int n = blockIdx.x * blockDim.x + threadIdx.x;
    if (n >= NN) return;
    float di = DINV[n];
#pragma unroll
    for (int i = 0; i < 3; i++) {
        float v = POS[n * 3 + i] + PACC[n * 3 + i] * di;
        POS[n * 3 + i] = v;
        if (outp) outp[n * 3 + i] = v;
    }
}

// ---------------- host ------------------------------------------------------------
extern "C" void kernel_launch(void* const* d_in, const int* in_sizes, int n_in,
                              void* d_out, int out_size)
{
    const float* x        = (const float*)d_in[0];
    const int*   ei32     = (const int*)d_in[1];
    const float* ea       = (const float*)d_in[2];
    const float* pos      = (const float*)d_in[3];
    const float* mW1      = (const float*)d_in[4];
    const float* mb1      = (const float*)d_in[5];
    const float* mW2      = (const float*)d_in[6];
    const float* mb2      = (const float*)d_in[7];
    const float* aW1      = (const float*)d_in[8];
    const float* ab1      = (const float*)d_in[9];
    const float* aW2      = (const float*)d_in[10];
    const float* ab2      = (const float*)d_in[11];
    const float* nW1      = (const float*)d_in[12];
    const float* nb1      = (const float*)d_in[13];
    const float* nW2      = (const float*)d_in[14];
    const float* nb2      = (const float*)d_in[15];
    float* outp = (float*)d_out;

    float *pU, *pV, *pS, *pINTRA, *pHID, *pXA, *pXB, *pPOS, *pPACC, *pW;
    float *pDEG, *pDINV, *pBM, *pC, *pD;
    int *pSRC, *pDST;
    cudaGetSymbolAddress((void**)&pU, g_U);
    cudaGetSymbolAddress((void**)&pV, g_V);
    cudaGetSymbolAddress((void**)&pS, g_S);
    cudaGetSymbolAddress((void**)&pINTRA, g_INTRA);
    cudaGetSymbolAddress((void**)&pHID, g_HID);
    cudaGetSymbolAddress((void**)&pXA, g_XA);
    cudaGetSymbolAddress((void**)&pXB, g_XB);
    cudaGetSymbolAddress((void**)&pPOS, g_POS);
    cudaGetSymbolAddress((void**)&pPACC, g_POSACC);
    cudaGetSymbolAddress((void**)&pW, g_W);
    cudaGetSymbolAddress((void**)&pDEG, g_DEG);
    cudaGetSymbolAddress((void**)&pDINV, g_DINV);
    cudaGetSymbolAddress((void**)&pBM, g_BMASK);
    cudaGetSymbolAddress((void**)&pC, g_C);
    cudaGetSymbolAddress((void**)&pD, g_D);
    cudaGetSymbolAddress((void**)&pSRC, g_SRC);
    cudaGetSymbolAddress((void**)&pDST, g_DST);

    static int attr_done = 0;
    if (!attr_done) {
        cudaFuncSetAttribute(fused_edge, cudaFuncAttributeMaxDynamicSharedMemorySize, 52224);
        attr_done = 1;
    }

    cudaMemcpyAsync(pPOS, pos, (size_t)NN * 3 * sizeof(float), cudaMemcpyDeviceToDevice);
    convert_idx<<<(NE + 255) / 256, 256>>>(ei32, pSRC, pDST);
    cudaMemsetAsync(pDEG, 0, (size_t)NN * sizeof(float));
    deg_kernel<<<(NE + 255) / 256, 256>>>(pDST, pDEG);
    dinv_kernel<<<(NN + 255) / 256, 256>>>(pDEG, pDINV, pBM);

    const float* xc = x;
    float* xn = pXA;

    for (int l = 0; l < 3; l++) {
        const int last = (l == 2);
        const float* mW1l = mW1 + (long)l * 384 * 128;
        const float* mb1l = mb1 + (long)l * 128;
        const float* mW2l = mW2 + (long)l * 128 * 128;
        const float* mb2l = mb2 + (long)l * 128;
        const float* aW1l = aW1 + (long)l * 128 * 256;
        const float* ab1l = ab1 + (long)l * 256;
        const float* aW2l = aW2 + (long)l * 256;
        const float* ab2l = ab2 + (long)l;
        const float* nW1l = nW1 + (long)l * 256 * 256;
        const float* nb1l = nb1 + (long)l * 256;
        const float* nW2l = nW2 + (long)l * 256 * 128;
        const float* nb2l = nb2 + (long)l * 128;

        if (!last) cudaMemsetAsync(pS, 0, (size_t)NN * HH * sizeof(float));
        cudaMemsetAsync(pPACC, 0, (size_t)NN * 3 * sizeof(float));

        prep_kernel<<<129, 256>>>(mW2l, aW1l, mb2l, ab1l, pC, pD);

        dim3 gN(1, (NN + 127) / 128);
        gemm_tf32<<<gN, 256>>>(xc, nullptr, mW1l, nullptr, pU, NN, 128, 128, 0, nullptr, nullptr);
        gemm_tf32<<<gN, 256>>>(xc, nullptr, mW1l + 128 * 128, nullptr, pV, NN, 128, 128, 0, nullptr, nullptr);

        fused_edge<<<(NE + 63) / 64, 256, 52224>>>(
            ea, mW1l + 256 * 128, mb1l, pU, pV, pSRC, pDST,
            pC, pD, aW2l, pS, pW, last ? 0 : 1);

        pos_edge_kernel<<<(NE + 255) / 256, 256>>>(pSRC, pDST, pW, ab2l, pPOS, pPACC);
        pos_apply_kernel<<<(NN + 255) / 256, 256>>>(pPOS, pPACC, pDINV, last ? outp : nullptr);

        if (!last) {
            gemm_tf32<<<gN, 256>>>(pS, nullptr, mW2l, mb2l, pINTRA, NN, 128, 128, 0, pDINV, pBM);
            dim3 gH(2, (NN + 127) / 128);
            gemm_tf32<<<gH, 256>>>(xc, pINTRA, nW1l, nb1l, pHID, NN, 256, 256, 1, nullptr, nullptr);
            gemm_tf32<<<gN, 256>>>(pHID, nullptr, nW2l, nb2l, xn, NN, 256, 128, 0, nullptr, nullptr);
            xc = xn;
            xn = (xn == pXA) ? pXB : pXA;
        }
    }
}

// round 11
// speedup vs baseline: 4.2481x; 1.1630x over previous
#include <cuda_runtime.h>
#include <cstdint>

#define NN 50000
#define NE 500000
#define HH 128

// ---------------- scratch (device globals; no cudaMalloc allowed) ----------------
__device__ float g_U[NN * HH];
__device__ float g_V[NN * HH];
__device__ float g_S[NN * HH];          // segment sum of relu(h)
__device__ float g_INTRA[NN * HH];
__device__ float g_HID[NN * 2 * HH];
__device__ float g_XA[NN * HH];
__device__ float g_XB[NN * HH];
__device__ float g_POS[NN * 3];
__device__ float g_POSACC[NN * 3];
__device__ float g_DEG[NN];
__device__ float g_DINV[NN];
__device__ float g_BMASK[NN];
__device__ float g_C[HH * 256];         // W2 @ aW1
__device__ float g_D[256];              // b2 @ aW1 + ab1
__device__ int   g_SRC[NE];
__device__ int   g_DST[NE];

// ---------------- mma helper (raw fp32 bits; tf32 HW truncates mantissa) ----------
__device__ __forceinline__ void mma8(float c[4],
                                     unsigned a0, unsigned a1, unsigned a2, unsigned a3,
                                     unsigned b0, unsigned b1) {
    asm("mma.sync.aligned.m16n8k8.row.col.f32.tf32.tf32.f32 "
        "{%0,%1,%2,%3},{%4,%5,%6,%7},{%8,%9},{%0,%1,%2,%3};"
        : "+f"(c[0]), "+f"(c[1]), "+f"(c[2]), "+f"(c[3])
        : "r"(a0), "r"(a1), "r"(a2), "r"(a3), "r"(b0), "r"(b1));
}

// -------- index normalization: handles harness storing edge_index as int32 OR int64
__global__ void convert_idx(const int* __restrict__ ei32, int* __restrict__ SRC,
                            int* __restrict__ DST)
{
    bool is64 = (ei32[1] == 0 && ei32[3] == 0 && ei32[5] == 0 && ei32[7] == 0);
    int e = blockIdx.x * blockDim.x + threadIdx.x;
    if (e >= NE) return;
    if (is64) {
        const long long* e64 = (const long long*)ei32;
        SRC[e] = (int)e64[e];
        DST[e] = (int)e64[NE + e];
    } else {
        SRC[e] = ei32[e];
        DST[e] = ei32[NE + e];
    }
}

// ---------------- tf32 GEMM: 128(M) x 128(N) block, 256 threads (node side) -------
#define SA_STR 20
#define SB_STR 136
__global__ void __launch_bounds__(256) gemm_tf32(
    const float* __restrict__ A, const float* __restrict__ A2,
    const float* __restrict__ B, const float* __restrict__ bias,
    float* __restrict__ Cout, int M, int K, int Ncols,
    int reluFlag, const float* __restrict__ rowscale, const float* __restrict__ rowmask)
{
    __shared__ unsigned sA[128 * SA_STR];
    __shared__ unsigned sB[16 * SB_STR];
    const int bm = blockIdx.y * 128;
    const int bn = blockIdx.x * 128;
    const int tid = threadIdx.x;
    const int lane = tid & 31;
    const int warp = tid >> 5;
    const int wm = warp >> 1;   // 0..3
    const int wn = warp & 1;    // 0..1

    const int arow = tid >> 1;
    const int ac0  = (tid & 1) << 3;
    const int brow = tid >> 5;
    const int bn4  = (tid & 31) << 2;

    float acc[2][8][4];
#pragma unroll
    for (int i = 0; i < 2; i++)
#pragma unroll
        for (int j = 0; j < 8; j++)
#pragma unroll
            for (int q = 0; q < 4; q++) acc[i][j][q] = 0.f;

    uint4 pa0, pa1, pb0, pb1;
    {
        int grow = bm + arow;
        pa0 = make_uint4(0, 0, 0, 0); pa1 = make_uint4(0, 0, 0, 0);
        if (grow < M) {
            int gk = ac0;
            const float* s;
            if (A2) s = (gk < HH) ? (A + (long)grow * HH + gk) : (A2 + (long)grow * HH + gk - HH);
            else    s = A + (long)grow * K + gk;
            pa0 = *(const uint4*)s;
            pa1 = *(const uint4*)(s + 4);
        }
        pb0 = *(const uint4*)(B + (long)brow * Ncols + bn + bn4);
        pb1 = *(const uint4*)(B + (long)(brow + 8) * Ncols + bn + bn4);
    }

    for (int k0 = 0; k0 < K; k0 += 16) {
        *(uint4*)&sA[arow * SA_STR + ac0]     = pa0;
        *(uint4*)&sA[arow * SA_STR + ac0 + 4] = pa1;
        *(uint4*)&sB[brow * SB_STR + bn4]       = pb0;
        *(uint4*)&sB[(brow + 8) * SB_STR + bn4] = pb1;
        __syncthreads();

        int kn = k0 + 16;
        if (kn < K) {
            int grow = bm + arow;
            pa0 = make_uint4(0, 0, 0, 0); pa1 = make_uint4(0, 0, 0, 0);
            if (grow < M) {
                int gk = kn + ac0;
                const float* s;
                if (A2) s = (gk < HH) ? (A + (long)grow * HH + gk) : (A2 + (long)grow * HH + gk - HH);
                else    s = A + (long)grow * K + gk;
                pa0 = *(const uint4*)s;
                pa1 = *(const uint4*)(s + 4);
            }
            pb0 = *(const uint4*)(B + (long)(kn + brow) * Ncols + bn + bn4);
            pb1 = *(const uint4*)(B + (long)(kn + brow + 8) * Ncols + bn + bn4);
        }

#pragma unroll
        for (int ks = 0; ks < 2; ks++) {
            const int kk = ks * 8 + (lane & 3);
            unsigned a[2][4];
#pragma unroll
            for (int it = 0; it < 2; it++) {
                int rb = wm * 32 + it * 16 + (lane >> 2);
                a[it][0] = sA[rb * SA_STR + kk];
                a[it][1] = sA[(rb + 8) * SA_STR + kk];
                a[it][2] = sA[rb * SA_STR + kk + 4];
                a[it][3] = sA[(rb + 8) * SA_STR + kk + 4];
            }
#pragma unroll
            for (int jt = 0; jt < 8; jt++) {
                int nb = wn * 64 + jt * 8 + (lane >> 2);
                unsigned b0 = sB[kk * SB_STR + nb];
                unsigned b1 = sB[(kk + 4) * SB_STR + nb];
                mma8(acc[0][jt], a[0][0], a[0][1], a[0][2], a[0][3], b0, b1);
                mma8(acc[1][jt], a[1][0], a[1][1], a[1][2], a[1][3], b0, b1);
            }
        }
        __syncthreads();
    }

#pragma unroll
    for (int it = 0; it < 2; it++) {
        int row0 = bm + wm * 32 + it * 16 + (lane >> 2);
#pragma unroll
        for (int h = 0; h < 2; h++) {
            int row = row0 + h * 8;
            if (row >= M) continue;
            float rs = rowscale ? rowscale[row] : 1.f;
            float rm = rowmask ? rowmask[row] : 1.f;
#pragma unroll
            for (int jt = 0; jt < 8; jt++) {
                int col = bn + wn * 64 + jt * 8 + ((lane & 3) << 1);
                float v0 = acc[it][jt][h * 2 + 0] * rs;
                float v1 = acc[it][jt][h * 2 + 1] * rs;
                if (bias) { v0 += bias[col] * rm; v1 += bias[col + 1] * rm; }
                if (reluFlag) { v0 = fmaxf(v0, 0.f); v1 = fmaxf(v1, 0.f); }
                *(float2*)(Cout + (long)row * Ncols + col) = make_float2(v0, v1);
            }
        }
    }
}

// ---------------- FUSED edge kernel: 128 edges per block ---------------------------
// phase 1 : H = relu(ea@W1c + b1 + U[dst] + V[src]) (tf32 GEMM, K=128) -> shared sH
// phase 1b: S[dst] += H (red.global.add.v4.f32, if doS)
// phase 2 : g = relu(H@C + D); w[e] = g . aW2  (two 128-col halves, tf32 from sH)
// tail    : equivariant pos accumulation into PACC (fused, no w round-trip)
// Dynamic shared layout (bytes):
//  sH   @ 0     : 128*132*4 = 67584
//  sAe  @ 67584 : 128*20*4  = 10240   (phase-1 A staging)
//  sB1  @ 77824 : 16*136*4  = 8704    (phase-1 B staging; end 86528)
//  sB2  @ 67584 : 16*136*4  = 8704    (phase-2 B staging; overlays sAe)
//  sDst @ 86528 (512), sSrc @ 87040 (512), red @ 87552 (128*2*4=1024) -> total 88576
#define SH_STR 132
__global__ void __launch_bounds__(256) fused_edge(
    const float* __restrict__ EA, const float* __restrict__ W1c,
    const float* __restrict__ b1,
    const float* __restrict__ U, const float* __restrict__ V,
    const int* __restrict__ SRC, const int* __restrict__ DST,
    const float* __restrict__ Cm, const float* __restrict__ D,
    const float* __restrict__ aW2, const float* __restrict__ ab2,
    const float* __restrict__ POS,
    float* __restrict__ S, float* __restrict__ PACC, int doS)
{
    extern __shared__ char smem[];
    float*    sH  = (float*)smem;
    unsigned* sAe = (unsigned*)(smem + 67584);
    unsigned* sB1 = (unsigned*)(smem + 77824);
    unsigned* sB2 = (unsigned*)(smem + 67584);
    int*   sDst = (int*)(smem + 86528);
    int*   sSrc = (int*)(smem + 87040);
    float (*red)[2] = (float(*)[2])(smem + 87552);

    const int bm = blockIdx.x * 128;
    const int tid = threadIdx.x;
    const int lane = tid & 31;
    const int warp = tid >> 5;
    const int wm = warp >> 1;   // 0..3
    const int wn = warp & 1;    // 0..1

    // stage edge indices
    if (tid < 128) {
        int e = bm + tid;
        sDst[tid] = (e < NE) ? DST[e] : 0;
        sSrc[tid] = (e < NE) ? SRC[e] : 0;
    }

    const int arow = tid >> 1;          // 0..127
    const int ac0  = (tid & 1) << 3;    // 0 or 8
    const int brow = tid >> 5;          // 0..7 (+8)
    const int bn4  = (tid & 31) << 2;   // 0..124

    // ---------------- phase 1: H = EA @ W1c (128 x 128, K=128) ----------------
    {
        float acc[2][8][4];
#pragma unroll
        for (int i = 0; i < 2; i++)
#pragma unroll
            for (int j = 0; j < 8; j++)
#pragma unroll
                for (int q = 0; q < 4; q++) acc[i][j][q] = 0.f;

        uint4 pa0, pa1, pb0, pb1;
        {
            int grow = bm + arow;
            pa0 = make_uint4(0, 0, 0, 0); pa1 = make_uint4(0, 0, 0, 0);
            if (grow < NE) {
                const float* s = EA + (long)grow * HH + ac0;
                pa0 = *(const uint4*)s;
                pa1 = *(const uint4*)(s + 4);
            }
            pb0 = *(const uint4*)(W1c + (long)brow * HH + bn4);
            pb1 = *(const uint4*)(W1c + (long)(brow + 8) * HH + bn4);
        }

        for (int k0 = 0; k0 < 128; k0 += 16) {
            *(uint4*)&sAe[arow * SA_STR + ac0]     = pa0;
            *(uint4*)&sAe[arow * SA_STR + ac0 + 4] = pa1;
            *(uint4*)&sB1[brow * SB_STR + bn4]       = pb0;
            *(uint4*)&sB1[(brow + 8) * SB_STR + bn4] = pb1;
            __syncthreads();

            int kn = k0 + 16;
            if (kn < 128) {
                int grow = bm + arow;
                pa0 = make_uint4(0, 0, 0, 0); pa1 = make_uint4(0, 0, 0, 0);
                if (grow < NE) {
                    const float* s = EA + (long)grow * HH + kn + ac0;
                    pa0 = *(const uint4*)s;
                    pa1 = *(const uint4*)(s + 4);
                }
                pb0 = *(const uint4*)(W1c + (long)(kn + brow) * HH + bn4);
                pb1 = *(const uint4*)(W1c + (long)(kn + brow + 8) * HH + bn4);
            }

#pragma unroll
            for (int ks = 0; ks < 2; ks++) {
                const int kk = ks * 8 + (lane & 3);
                unsigned a[2][4];
#pragma unroll
                for (int it = 0; it < 2; it++) {
                    int rb = wm * 32 + it * 16 + (lane >> 2);
                    a[it][0] = sAe[rb * SA_STR + kk];
                    a[it][1] = sAe[(rb + 8) * SA_STR + kk];
                    a[it][2] = sAe[rb * SA_STR + kk + 4];
                    a[it][3] = sAe[(rb + 8) * SA_STR + kk + 4];
                }
#pragma unroll
                for (int jt = 0; jt < 8; jt++) {
                    int nb = wn * 64 + jt * 8 + (lane >> 2);
                    unsigned b0 = sB1[kk * SB_STR + nb];
                    unsigned b1r = sB1[(kk + 4) * SB_STR + nb];
                    mma8(acc[0][jt], a[0][0], a[0][1], a[0][2], a[0][3], b0, b1r);
                    mma8(acc[1][jt], a[1][0], a[1][1], a[1][2], a[1][3], b0, b1r);
                }
            }
            __syncthreads();
        }

        // epilogue: + b1 + U[dst] + V[src], relu, -> sH
#pragma unroll
        for (int it = 0; it < 2; it++) {
#pragma unroll
            for (int h = 0; h < 2; h++) {
                int r = wm * 32 + it * 16 + (lane >> 2) + h * 8;
                bool valid = (bm + r) < NE;
                int d = sDst[r], s = sSrc[r];
#pragma unroll
                for (int jt = 0; jt < 8; jt++) {
                    int c = wn * 64 + jt * 8 + ((lane & 3) << 1);
                    float v0 = 0.f, v1 = 0.f;
                    if (valid) {
                        float2 uu = *(const float2*)(U + (long)d * HH + c);
                        float2 vv = *(const float2*)(V + (long)s * HH + c);
                        v0 = fmaxf(acc[it][jt][h * 2 + 0] + b1[c]     + uu.x + vv.x, 0.f);
                        v1 = fmaxf(acc[it][jt][h * 2 + 1] + b1[c + 1] + uu.y + vv.y, 0.f);
                    }
                    *(float2*)&sH[r * SH_STR + c] = make_float2(v0, v1);
                }
            }
        }
    }
    __syncthreads();

    // ---------------- phase 1b: S[dst] += H (vector red) ----------------
    if (doS) {
        int r = tid >> 1;
        int cb = (tid & 1) << 6;   // 0 or 64
        if (bm + r < NE) {
            float* base = S + (long)sDst[r] * HH + cb;
            const float* hrow = sH + r * SH_STR + cb;
#pragma unroll
            for (int p = 0; p < 16; p++) {
                float4 v = *(const float4*)(hrow + p * 4);
                if (v.x != 0.f || v.y != 0.f || v.z != 0.f || v.w != 0.f) {
                    asm volatile("red.global.add.v4.f32 [%0], {%1,%2,%3,%4};"
                                 :: "l"(base + p * 4), "f"(v.x), "f"(v.y), "f"(v.z), "f"(v.w)
                                 : "memory");
                }
            }
        }
    }

    // ---------------- phase 2: w = (relu(H@C + D)) . aW2, two 128-col halves ------
    float ws[2][2];
    ws[0][0] = ws[0][1] = ws[1][0] = ws[1][1] = 0.f;
    {
#pragma unroll 1
        for (int ch = 0; ch < 2; ch++) {
            float acc2[2][8][4];
#pragma unroll
            for (int i = 0; i < 2; i++)
#pragma unroll
                for (int j = 0; j < 8; j++)
#pragma unroll
                    for (int q = 0; q < 4; q++) acc2[i][j][q] = 0.f;

            uint4 pb0, pb1;
            pb0 = *(const uint4*)(Cm + (long)brow * 256 + ch * 128 + bn4);
            pb1 = *(const uint4*)(Cm + (long)(brow + 8) * 256 + ch * 128 + bn4);

            for (int k0 = 0; k0 < 128; k0 += 16) {
                __syncthreads();
                *(uint4*)&sB2[brow * SB_STR + bn4]       = pb0;
                *(uint4*)&sB2[(brow + 8) * SB_STR + bn4] = pb1;
                __syncthreads();

                int kn = k0 + 16;
                if (kn < 128) {
                    pb0 = *(const uint4*)(Cm + (long)(kn + brow) * 256 + ch * 128 + bn4);
                    pb1 = *(const uint4*)(Cm + (long)(kn + brow + 8) * 256 + ch * 128 + bn4);
                }

#pragma unroll
                for (int ks = 0; ks < 2; ks++) {
                    const int kkl = ks * 8 + (lane & 3);
                    const int kkg = k0 + kkl;
                    unsigned a[2][4];
#pragma unroll
                    for (int it = 0; it < 2; it++) {
                        int rb = wm * 32 + it * 16 + (lane >> 2);
                        a[it][0] = __float_as_uint(sH[rb * SH_STR + kkg]);
                        a[it][1] = __float_as_uint(sH[(rb + 8) * SH_STR + kkg]);
                        a[it][2] = __float_as_uint(sH[rb * SH_STR + kkg + 4]);
                        a[it][3] = __float_as_uint(sH[(rb + 8) * SH_STR + kkg + 4]);
                    }
#pragma unroll
                    for (int jt = 0; jt < 8; jt++) {
                        int nb = wn * 64 + jt * 8 + (lane >> 2);
                        unsigned b0 = sB2[kkl * SB_STR + nb];
                        unsigned b1r = sB2[(kkl + 4) * SB_STR + nb];
                        mma8(acc2[0][jt], a[0][0], a[0][1], a[0][2], a[0][3], b0, b1r);
                        mma8(acc2[1][jt], a[1][0], a[1][1], a[1][2], a[1][3], b0, b1r);
                    }
                }
            }

            // fold this half into per-row partial dots
#pragma unroll
            for (int it = 0; it < 2; it++) {
#pragma unroll
                for (int jt = 0; jt < 8; jt++) {
                    int col = ch * 128 + wn * 64 + jt * 8 + ((lane & 3) << 1);
                    float d0 = D[col], d1 = D[col + 1];
                    float w0 = aW2[col], w1 = aW2[col + 1];
                    ws[it][0] += fmaxf(acc2[it][jt][0] + d0, 0.f) * w0
                               + fmaxf(acc2[it][jt][1] + d1, 0.f) * w1;
                    ws[it][1] += fmaxf(acc2[it][jt][2] + d0, 0.f) * w0
                               + fmaxf(acc2[it][jt][3] + d1, 0.f) * w1;
                }
            }
        }
    }

    // cross-lane reduce (over lane&3) and stage per-row partials
#pragma unroll
    for (int it = 0; it < 2; it++) {
#pragma unroll
        for (int h = 0; h < 2; h++) {
            float s = ws[it][h];
            s += __shfl_xor_sync(0xffffffffu, s, 1);
            s += __shfl_xor_sync(0xffffffffu, s, 2);
            if ((lane & 3) == 0) {
                int r = wm * 32 + it * 16 + (lane >> 2) + h * 8;
                red[r][wn] = s;
            }
        }
    }
    __syncthreads();

    // tail: fused equivariant pos accumulation
    if (tid < 128) {
        int e = bm + tid;
        if (e < NE) {
            float w = red[tid][0] + red[tid][1] + ab2[0];
            int src = sSrc[tid], dst = sDst[tid];
            float rx = POS[src * 3 + 0] - POS[dst * 3 + 0];
            float ry = POS[src * 3 + 1] - POS[dst * 3 + 1];
            float rz = POS[src * 3 + 2] - POS[dst * 3 + 2];
            float dist = sqrtf(rx * rx + ry * ry + rz * rz);
            float sc = w / dist;
            atomicAdd(&PACC[dst * 3 + 0], sc * rx);
            atomicAdd(&PACC[dst * 3 + 1], sc * ry);
            atomicAdd(&PACC[dst * 3 + 2], sc * rz);
        }
    }
}

// ---------------- small per-layer prep: C = W2@aW1, D = b2@aW1 + ab1 --------------
__global__ void prep_kernel(const float* __restrict__ W2, const float* __restrict__ aW1,
                            const float* __restrict__ b2, const float* __restrict__ ab1,
                            float* __restrict__ C, float* __restrict__ D)
{
    int j = threadIdx.x;   // 0..255
    int k = blockIdx.x;    // 0..128
    if (k < 128) {
        float s = 0.f;
#pragma unroll 8
        for (int t = 0; t < 128; t++) s += W2[k * 128 + t] * aW1[t * 256 + j];
        C[k * 256 + j] = s;
    } else {
        float s = ab1[j];
#pragma unroll 8
        for (int t = 0; t < 128; t++) s += b2[t] * aW1[t * 256 + j];
        D[j] = s;
    }
}

// ---------------- degree / denom -------------------------------------------------
__global__ void deg_kernel(const int* __restrict__ DST, float* __restrict__ DEG)
{
    int e = blockIdx.x * blockDim.x + threadIdx.x;
    if (e < NE) atomicAdd(&DEG[DST[e]], 1.f);
}

__global__ void dinv_kernel(const float* __restrict__ DEG, float* __restrict__ DINV,
                            float* __restrict__ BM)
{
    int n = blockIdx.x * blockDim.x + threadIdx.x;
    if (n >= NN) return;
    float d = DEG[n];
    DINV[n] = 1.f / fmaxf(d, 1.f);
    BM[n] = (d > 0.f) ? 1.f : 0.f;
}

__global__ void pos_apply_kernel(float* __restrict__ POS, const float* __restrict__ PACC,
                                 const float* __restrict__ DINV, float* __restrict__ outp)
{
    int n = blockIdx.x * blockDim.x + threadIdx.x;
    if (n >= NN) return;
    float di = DINV[n];
#pragma unroll
    for (int i = 0; i < 3; i++) {
        float v = POS[n * 3 + i] + PACC[n * 3 + i] * di;
        POS[n * 3 + i] = v;
        if (outp) outp[n * 3 + i] = v;
    }
}

// ---------------- host ------------------------------------------------------------
extern "C" void kernel_launch(void* const* d_in, const int* in_sizes, int n_in,
                              void* d_out, int out_size)
{
    const float* x        = (const float*)d_in[0];
    const int*   ei32     = (const int*)d_in[1];
    const float* ea       = (const float*)d_in[2];
    const float* pos      = (const float*)d_in[3];
    const float* mW1      = (const float*)d_in[4];
    const float* mb1      = (const float*)d_in[5];
    const float* mW2      = (const float*)d_in[6];
    const float* mb2      = (const float*)d_in[7];
    const float* aW1      = (const float*)d_in[8];
    const float* ab1      = (const float*)d_in[9];
    const float* aW2      = (const float*)d_in[10];
    const float* ab2      = (const float*)d_in[11];
    const float* nW1      = (const float*)d_in[12];
    const float* nb1      = (const float*)d_in[13];
    const float* nW2      = (const float*)d_in[14];
    const float* nb2      = (const float*)d_in[15];
    float* outp = (float*)d_out;

    float *pU, *pV, *pS, *pINTRA, *pHID, *pXA, *pXB, *pPOS, *pPACC;
    float *pDEG, *pDINV, *pBM, *pC, *pD;
    int *pSRC, *pDST;
    cudaGetSymbolAddress((void**)&pU, g_U);
    cudaGetSymbolAddress((void**)&pV, g_V);
    cudaGetSymbolAddress((void**)&pS, g_S);
    cudaGetSymbolAddress((void**)&pINTRA, g_INTRA);
    cudaGetSymbolAddress((void**)&pHID, g_HID);
    cudaGetSymbolAddress((void**)&pXA, g_XA);
    cudaGetSymbolAddress((void**)&pXB, g_XB);
    cudaGetSymbolAddress((void**)&pPOS, g_POS);
    cudaGetSymbolAddress((void**)&pPACC, g_POSACC);
    cudaGetSymbolAddress((void**)&pDEG, g_DEG);
    cudaGetSymbolAddress((void**)&pDINV, g_DINV);
    cudaGetSymbolAddress((void**)&pBM, g_BMASK);
    cudaGetSymbolAddress((void**)&pC, g_C);
    cudaGetSymbolAddress((void**)&pD, g_D);
    cudaGetSymbolAddress((void**)&pSRC, g_SRC);
    cudaGetSymbolAddress((void**)&pDST, g_DST);

    static int attr_done = 0;
    if (!attr_done) {
        cudaFuncSetAttribute(fused_edge, cudaFuncAttributeMaxDynamicSharedMemorySize, 88576);
        attr_done = 1;
    }

    cudaMemcpyAsync(pPOS, pos, (size_t)NN * 3 * sizeof(float), cudaMemcpyDeviceToDevice);
    convert_idx<<<(NE + 255) / 256, 256>>>(ei32, pSRC, pDST);
    cudaMemsetAsync(pDEG, 0, (size_t)NN * sizeof(float));
    deg_kernel<<<(NE + 255) / 256, 256>>>(pDST, pDEG);
    dinv_kernel<<<(NN + 255) / 256, 256>>>(pDEG, pDINV, pBM);

    const float* xc = x;
    float* xn = pXA;

    for (int l = 0; l < 3; l++) {
        const int last = (l == 2);
        const float* mW1l = mW1 + (long)l * 384 * 128;
        const float* mb1l = mb1 + (long)l * 128;
        const float* mW2l = mW2 + (long)l * 128 * 128;
        const float* mb2l = mb2 + (long)l * 128;
        const float* aW1l = aW1 + (long)l * 128 * 256;
        const float* ab1l = ab1 + (long)l * 256;
        const float* aW2l = aW2 + (long)l * 256;
        const float* ab2l = ab2 + (long)l;
        const float* nW1l = nW1 + (long)l * 256 * 256;
        const float* nb1l = nb1 + (long)l * 256;
        const float* nW2l = nW2 + (long)l * 256 * 128;
        const float* nb2l = nb2 + (long)l * 128;

        if (!last) cudaMemsetAsync(pS, 0, (size_t)NN * HH * sizeof(float));
        cudaMemsetAsync(pPACC, 0, (size_t)NN * 3 * sizeof(float));

        prep_kernel<<<129, 256>>>(mW2l, aW1l, mb2l, ab1l, pC, pD);

        dim3 gN(1, (NN + 127) / 128);
        gemm_tf32<<<gN, 256>>>(xc, nullptr, mW1l, nullptr, pU, NN, 128, 128, 0, nullptr, nullptr);
        gemm_tf32<<<gN, 256>>>(xc, nullptr, mW1l + 128 * 128, nullptr, pV, NN, 128, 128, 0, nullptr, nullptr);

        fused_edge<<<(NE + 127) / 128, 256, 88576>>>(
            ea, mW1l + 256 * 128, mb1l, pU, pV, pSRC, pDST,
            pC, pD, aW2l, ab2l, pPOS, pS, pPACC, last ? 0 : 1);

        pos_apply_kernel<<<(NN + 255) / 256, 256>>>(pPOS, pPACC, pDINV, last ? outp : nullptr);

        if (!last) {
            gemm_tf32<<<gN, 256>>>(pS, nullptr, mW2l, mb2l, pINTRA, NN, 128, 128, 0, pDINV, pBM);
            dim3 gH(2, (NN + 127) / 128);
            gemm_tf32<<<gH, 256>>>(xc, pINTRA, nW1l, nb1l, pHID, NN, 256, 256, 1, nullptr, nullptr);
            gemm_tf32<<<gN, 256>>>(pHID, nullptr, nW2l, nb2l, xn, NN, 256, 128, 0, nullptr, nullptr);
            xc = xn;
            xn = (xn == pXA) ? pXB : pXA;
        }
    }
}